// round 12
// baseline (speedup 1.0000x reference)
#include <cuda_runtime.h>
#include <cstdint>

#define N_MAX 25000
#define E_MAX 400000
#define CCH 64
#define ETHREADS 512
#define EGRID 296          /* 2 CTAs per SM x 148 SMs */
#define TILE 64
#define HSTR 65

static __device__ float4 d_x[N_MAX * CCH];   // up-projected  [N][C][4]
static __device__ float4 d_M[N_MAX * CCH];   // scatter accum [N][C][4]
static __device__ float  d_ef[E_MAX * 8];    // edge bessel feats
static __device__ float4 d_Y[E_MAX];         // sqrt3 * unit vec (w unused)
static __device__ float  d_U[4 * CCH];       // embW @ lin_up_W0[0]
static __device__ float  d_W0c[CCH * CCH];   // prod_lin_W0[0] @ lin_up_W0[1]
static __device__ float  d_W1c[CCH * CCH];   // prod_lin_W1[0] @ lin_up_W1[1]

__device__ __forceinline__ float silu_f(float v) {
    return v / (1.0f + __expf(-v));
}
__device__ __forceinline__ unsigned long long pack2(float x) {
    unsigned long long r;
    asm("mov.b64 %0, {%1, %1};" : "=l"(r) : "f"(x));
    return r;
}
__device__ __forceinline__ void fma2(unsigned long long &d, unsigned long long a, unsigned long long b) {
    asm("fma.rn.f32x2 %0, %1, %2, %0;" : "+l"(d) : "l"(a), "l"(b));
}
__device__ __forceinline__ float2 unpack2(unsigned long long v) {
    float2 r;
    asm("mov.b64 {%0, %1}, %2;" : "=f"(r.x), "=f"(r.y) : "l"(v));
    return r;
}

// ---------------------------------------------------------------------------
// Per-edge geometry (accurate sinf — MUFU __sinf is NOT accurate at 8pi)
// ---------------------------------------------------------------------------
__global__ void k_geom(const float* __restrict__ pos, const int* __restrict__ ei, int E_) {
    int e = blockIdx.x * blockDim.x + threadIdx.x;
    if (e >= E_) return;
    int s = ei[e];
    int r_ = ei[E_ + e];
    float vx = pos[3*s + 0] - pos[3*r_ + 0];
    float vy = pos[3*s + 1] - pos[3*r_ + 1];
    float vz = pos[3*s + 2] - pos[3*r_ + 2];
    float rr = sqrtf(vx*vx + vy*vy + vz*vz);
    rr = fmaxf(rr, 1e-6f);
    float inv_r = 1.0f / rr;
    const float SQRT3 = 1.7320508075688772f;
    float4 Y;
    Y.x = SQRT3 * vx * inv_r;
    Y.y = SQRT3 * vy * inv_r;
    Y.z = SQRT3 * vz * inv_r;
    Y.w = 0.0f;
    d_Y[e] = Y;
    float x = rr * 0.2f;
    float x2 = x * x;
    float x6 = x2 * x2 * x2;
    float fc = 1.0f - 28.0f*x6 + 48.0f*x6*x - 21.0f*x6*x2;
    fc = (x < 1.0f) ? fc : 0.0f;
    const float BC = 0.6324555320336759f;      // sqrt(2/5)
    const float PI_O_R = 0.6283185307179586f;  // pi/5
    float pref = BC * inv_r * fc;
    float ef[8];
    #pragma unroll
    for (int k = 0; k < 8; k++)
        ef[k] = pref * sinf((float)(k + 1) * PI_O_R * rr);
    float4* dst = (float4*)(d_ef + (size_t)e * 8);
    dst[0] = make_float4(ef[0], ef[1], ef[2], ef[3]);
    dst[1] = make_float4(ef[4], ef[5], ef[6], ef[7]);
}

// ---------------------------------------------------------------------------
// Weight prep (single block)
// ---------------------------------------------------------------------------
__global__ void __launch_bounds__(256) k_prepw(
    const float* __restrict__ embW, const float* __restrict__ LU0_l0,
    const float* __restrict__ PL0_l0, const float* __restrict__ LU0_l1,
    const float* __restrict__ PL1_l0, const float* __restrict__ LU1_l1)
{
    int tid = threadIdx.x;
    {
        int s = tid >> 6, j = tid & 63;
        float acc = 0.0f;
        for (int k = 0; k < 64; k++) acc += embW[s * 64 + k] * LU0_l0[k * 64 + j];
        d_U[tid] = acc;
    }
    for (int t = tid; t < 4096; t += 256) {
        int i = t >> 6, j = t & 63;
        float a0 = 0.0f, a1 = 0.0f;
        for (int k = 0; k < 64; k++) {
            a0 += PL0_l0[i * 64 + k] * LU0_l1[k * 64 + j];
            a1 += PL1_l0[i * 64 + k] * LU1_l1[k * 64 + j];
        }
        d_W0c[t] = a0;
        d_W1c[t] = a1;
    }
}

// ---------------------------------------------------------------------------
// Layer-0 seed: x = row-select of U (h1 == 0), zero M
// ---------------------------------------------------------------------------
__global__ void k_seed(const int* __restrict__ species, int N_) {
    int idx = blockIdx.x * blockDim.x + threadIdx.x;
    if (idx >= N_ * CCH) return;
    int n = idx >> 6, c = idx & 63;
    int sp = species[n];
    d_x[idx] = make_float4(d_U[sp * CCH + c], 0.0f, 0.0f, 0.0f);
    d_M[idx] = make_float4(0, 0, 0, 0);
}

// ---------------------------------------------------------------------------
// Persistent fused edge kernel: 2 CTAs per SM (independent barrier schedules).
// Each CTA-pair splits phase D's 64 output channels in half (half = bid&1);
// B and C are duplicated (cheap). 64-edge tiles, 512 threads, 64-reg cap.
// ---------------------------------------------------------------------------
#define SME_W1   0
#define SME_W2   512
#define SME_W3   4608
#define SME_HA   14848
#define SME_HB   19008
#define SME_EF   23168
#define SME_Y    23680
#define SME_SND  23936
#define SME_RCV  24000
#define SME_TOT  24064   // floats (94 KB)

template<bool FIRST>
__device__ __forceinline__ void emit_msg(float* dst, float4 xs, float4 Yv,
                                         float t0, float t1, float t2,
                                         float t3, float t4) {
    const float INV_SQRT3 = 0.5773502691896258f;
    const float INV_SQRT2 = 0.7071067811865475f;
    float m0, m1x, m1y, m1z;
    if (FIRST) {
        m0 = t0 * xs.x;
        float a = t1 * xs.x;
        m1x = a * Yv.x;
        m1y = a * Yv.y;
        m1z = a * Yv.z;
    } else {
        float dotv = xs.y * Yv.x + xs.z * Yv.y + xs.w * Yv.z;
        m0 = t0 * xs.x + t3 * dotv * INV_SQRT3;
        float cx = xs.z * Yv.z - xs.w * Yv.y;
        float cy = xs.w * Yv.x - xs.y * Yv.z;
        float cz = xs.y * Yv.y - xs.z * Yv.x;
        float a = t1 * xs.x;
        float t4s = t4 * INV_SQRT2;
        m1x = a * Yv.x + t2 * xs.y + t4s * cx;
        m1y = a * Yv.y + t2 * xs.z + t4s * cy;
        m1z = a * Yv.z + t2 * xs.w + t4s * cz;
    }
    asm volatile("red.global.add.v4.f32 [%0], {%1,%2,%3,%4};"
                 :: "l"(dst), "f"(m0), "f"(m1x), "f"(m1y), "f"(m1z)
                 : "memory");
}

template<bool FIRST>
__global__ void __launch_bounds__(ETHREADS, 2) k_edge(
    const int* __restrict__ ei,
    const float* __restrict__ W1g, const float* __restrict__ W2g,
    const float* __restrict__ W3g, int E_)
{
    extern __shared__ float sm[];
    float* sW1 = sm + SME_W1;
    float* sW2 = sm + SME_W2;
    float* sW3 = sm + SME_W3;    // compact half-channel W3: [64cc][NB*32]
    float* sHa = sm + SME_HA;    // [64][65]
    float* sHb = sm + SME_HB;    // [64][65]
    float* sEF = sm + SME_EF;
    float4* sY = (float4*)(sm + SME_Y);
    int* sSend = (int*)(sm + SME_SND);
    int* sRecv = (int*)(sm + SME_RCV);
    const int tid = threadIdx.x;
    constexpr int NB = FIRST ? 2 : 5;
    constexpr int NBW = NB * 32;
    const int half = blockIdx.x & 1;
    const int HB = half * 32;

    // one-time weight load (persistent block); W3 compacted to this half's cols
    for (int i = tid; i < 512; i += ETHREADS) sW1[i] = W1g[i];
    for (int i = tid; i < 4096; i += ETHREADS) sW2[i] = W2g[i];
    for (int i = tid; i < 64 * NBW; i += ETHREADS) {
        int cc = i / NBW, rem = i % NBW;
        int p = rem >> 5, c = rem & 31;
        sW3[i] = W3g[cc * 320 + p * 64 + HB + c];
    }

    int nTiles = (E_ + TILE - 1) / TILE;
    int tStep = gridDim.x >> 1;
    for (int t = blockIdx.x >> 1; t < nTiles; t += tStep) {
        long long base = (long long)t * TILE;
        __syncthreads();   // weights ready (iter 0) / prev tile consumers done
        if (tid < 128) {
            long long e = base + (tid >> 1);
            float4 v = make_float4(0, 0, 0, 0);
            if (e < E_) v = ((const float4*)d_ef)[e * 2 + (tid & 1)];
            ((float4*)sEF)[tid] = v;
        } else if (tid < 192) {
            int i = tid - 128;
            long long e = base + i;
            float4 y = make_float4(0, 0, 0, 0);
            if (e < E_) y = d_Y[e];
            sY[i] = y;
        } else if (tid < 256) {
            int i = tid - 192;
            long long e = base + i;
            int s = 0, r = -1;
            if (e < E_) { s = ei[e]; r = ei[E_ + e]; }
            sSend[i] = s;
            sRecv[i] = r;
        }
        __syncthreads();

        // Phase B: H1 = silu(EF @ W1)   [64 x 8]@[8 x 64]
        #pragma unroll
        for (int i = 0; i < (TILE * 64) / ETHREADS; i++) {
            int idx = tid + ETHREADS * i;
            int e = idx >> 6, j = idx & 63;
            float acc = 0.0f;
            #pragma unroll
            for (int k = 0; k < 8; k++) acc += sEF[e * 8 + k] * sW1[k * 64 + j];
            sHa[e * HSTR + j] = silu_f(acc);
        }
        __syncthreads();

        // Phase C: H2 = silu(H1 @ W2)  [64 x 64]@[64 x 64]; 2 edges x 4 cols
        {
            int e0 = (tid >> 4) << 1;
            int j0 = (tid & 15) << 2;
            unsigned long long acc[2][2] = {};
            #pragma unroll 4
            for (int cc = 0; cc < 64; cc++) {
                const unsigned long long* bp = (const unsigned long long*)&sW2[cc * 64 + j0];
                unsigned long long b0 = bp[0], b1 = bp[1];
                #pragma unroll
                for (int i = 0; i < 2; i++) {
                    unsigned long long a2 = pack2(sHa[(e0 + i) * HSTR + cc]);
                    fma2(acc[i][0], a2, b0);
                    fma2(acc[i][1], a2, b1);
                }
            }
            #pragma unroll
            for (int i = 0; i < 2; i++) {
                float2 p0 = unpack2(acc[i][0]);
                float2 p1 = unpack2(acc[i][1]);
                float* dst = &sHb[(e0 + i) * HSTR + j0];
                dst[0] = silu_f(p0.x);
                dst[1] = silu_f(p0.y);
                dst[2] = silu_f(p1.x);
                dst[3] = silu_f(p1.y);
            }
        }
        __syncthreads();

        // Phase D+E fused over THIS CTA's 32 channels.
        // Half-warp tile: 2 edges x 2 channels x NB paths.
        {
            int hw = tid >> 4;          // half-warp id, 0..31
            int lanec = tid & 15;
            int cb = lanec * 2;         // channel pair within the 32-ch half
            int eb = hw * 2;
            unsigned long long acc[2][NB];
            #pragma unroll
            for (int ii = 0; ii < 2; ii++)
                #pragma unroll
                for (int p = 0; p < NB; p++) acc[ii][p] = 0ull;

            #pragma unroll 2
            for (int cc = 0; cc < 64; cc++) {
                const float* wrow = &sW3[cc * NBW + cb];
                unsigned long long b[NB];
                #pragma unroll
                for (int p = 0; p < NB; p++)
                    b[p] = *(const unsigned long long*)(wrow + 32 * p);
                #pragma unroll
                for (int ii = 0; ii < 2; ii++) {
                    unsigned long long a2 = pack2(sHb[(eb + ii) * HSTR + cc]);
                    #pragma unroll
                    for (int p = 0; p < NB; p++) fma2(acc[ii][p], a2, b[p]);
                }
            }

            #pragma unroll 1
            for (int ii = 0; ii < 2; ii++) {
                int el = eb + ii;
                int r = sRecv[el];
                if (r < 0) continue;
                int s = sSend[el];
                float4 Yv = sY[el];
                const float4* xp = &d_x[(size_t)s * CCH + HB + cb];
                float4 xs0 = xp[0];
                float4 xs1 = xp[1];
                float2 t0 = unpack2(acc[ii][0]);
                float2 t1 = unpack2(acc[ii][1]);
                float2 t2 = make_float2(0, 0), t3 = make_float2(0, 0), t4 = make_float2(0, 0);
                if (!FIRST) {
                    t2 = unpack2(acc[ii][2]);
                    t3 = unpack2(acc[ii][3]);
                    t4 = unpack2(acc[ii][4]);
                }
                float* dst = (float*)&d_M[(size_t)r * CCH + HB + cb];
                emit_msg<FIRST>(dst,     xs0, Yv, t0.x, t1.x, t2.x, t3.x, t4.x);
                emit_msg<FIRST>(dst + 4, xs1, Yv, t0.y, t1.y, t2.y, t3.y, t4.y);
            }
        }
    }
}

// ---------------------------------------------------------------------------
// Fused post(l0)+up(l1) / final post
// ---------------------------------------------------------------------------
#define SMP_LW0 0
#define SMP_LW1 4096
#define SMP_PL0 8192
#define SMP_PL1 12288
#define SMP_PW0 16384
#define SMP_PW1 17152
#define SMP_A   17664
#define SMP_B   18688
#define SMP_TOT 19712   // floats

template<bool FINAL>
__global__ void __launch_bounds__(256) k_post(
    const int* __restrict__ species,
    const float* __restrict__ LW0g, const float* __restrict__ LW1g,
    const float* __restrict__ PW0g, const float* __restrict__ PW1g,
    const float* __restrict__ PL0g, const float* __restrict__ PL1g,
    float4* __restrict__ out, int N_)
{
    extern __shared__ float sm[];
    float* sLW0 = sm + SMP_LW0;
    float* sLW1 = sm + SMP_LW1;
    float* sPL0 = sm + SMP_PL0;
    float* sPL1 = sm + SMP_PL1;
    float* sPW0 = sm + SMP_PW0;
    float* sPW1 = sm + SMP_PW1;
    float4* sA = (float4*)(sm + SMP_A);
    float4* sB = (float4*)(sm + SMP_B);
    int tid = threadIdx.x;
    const float INV_SQRT3 = 0.5773502691896258f;
    for (int i = tid; i < 4096; i += 256) {
        sLW0[i] = LW0g[i];
        sLW1[i] = LW1g[i];
        sPL0[i] = PL0g[i];
        sPL1[i] = PL1g[i];
    }
    for (int i = tid; i < 768; i += 256) sPW0[i] = PW0g[i];
    for (int i = tid; i < 512; i += 256) sPW1[i] = PW1g[i];
    __syncthreads();

    int base = blockIdx.x * 64;
    int c = tid & 63, sub = tid >> 6;
    for (int g = 0; g < 16; g++) {
        int n = base + g * 4 + sub;
        bool act = n < N_;
        if (act) {
            float4 mv = d_M[(size_t)n * CCH + c];
            mv.x *= 0.0625f; mv.y *= 0.0625f; mv.z *= 0.0625f; mv.w *= 0.0625f;
            sA[sub * CCH + c] = mv;
        }
        __syncthreads();
        if (act) {
            float h0 = 0, h1x = 0, h1y = 0, h1z = 0;
            const float4* ar = &sA[sub * CCH];
            #pragma unroll 8
            for (int cc = 0; cc < 64; cc++) {
                float4 a = ar[cc];
                float w0 = sLW0[cc * 64 + c];
                float w1 = sLW1[cc * 64 + c];
                h0 += a.x * w0;
                h1x += a.y * w1;
                h1y += a.z * w1;
                h1z += a.w * w1;
            }
            int sp = species[n];
            float nrm = (h1x * h1x + h1y * h1y + h1z * h1z) * INV_SQRT3;
            const float* p0 = &sPW0[sp * 192 + c];
            float b0 = p0[0] * h0 + p0[64] * h0 * h0 + p0[128] * nrm;
            const float* p1 = &sPW1[sp * 128 + c];
            float q = p1[0] + p1[64] * h0;
            sB[sub * CCH + c] = make_float4(b0, q * h1x, q * h1y, q * h1z);
        }
        __syncthreads();
        if (act) {
            float o0 = 0, o1 = 0, o2 = 0, o3 = 0;
            const float4* br = &sB[sub * CCH];
            #pragma unroll 8
            for (int cc = 0; cc < 64; cc++) {
                float4 b = br[cc];
                float w0 = sPL0[cc * 64 + c];
                float w1 = sPL1[cc * 64 + c];
                o0 += b.x * w0;
                o1 += b.y * w1;
                o2 += b.z * w1;
                o3 += b.w * w1;
            }
            if (FINAL) {
                out[(size_t)n * CCH + c] = make_float4(o0, o1, o2, o3);
            } else {
                d_x[(size_t)n * CCH + c] = make_float4(o0, o1, o2, o3);
                d_M[(size_t)n * CCH + c] = make_float4(0, 0, 0, 0);
            }
        }
        __syncthreads();
    }
}

// ---------------------------------------------------------------------------
extern "C" void kernel_launch(void* const* d_in, const int* in_sizes, int n_in,
                              void* d_out, int out_size) {
    const float* positions    = (const float*)d_in[0];
    const int*   species      = (const int*)d_in[1];
    const int*   edge_index   = (const int*)d_in[2];
    const float* node_embed_W = (const float*)d_in[3];
    const float* lin_up_W0    = (const float*)d_in[4];
    const float* lin_up_W1    = (const float*)d_in[5];
    const float* mlp_W1       = (const float*)d_in[6];
    const float* mlp_W2       = (const float*)d_in[7];
    const float* mlp_W3       = (const float*)d_in[8];
    const float* lin_W0       = (const float*)d_in[9];
    const float* lin_W1       = (const float*)d_in[10];
    const float* prod_W0      = (const float*)d_in[11];
    const float* prod_W1      = (const float*)d_in[12];
    const float* prod_lin_W0  = (const float*)d_in[13];
    const float* prod_lin_W1  = (const float*)d_in[14];

    int N_ = in_sizes[0] / 3;
    int E_ = in_sizes[2] / 2;

    size_t smemE = (size_t)SME_TOT * 4;
    size_t smemP = (size_t)SMP_TOT * 4;
    cudaFuncSetAttribute(k_edge<true>,  cudaFuncAttributeMaxDynamicSharedMemorySize, (int)smemE);
    cudaFuncSetAttribute(k_edge<false>, cudaFuncAttributeMaxDynamicSharedMemorySize, (int)smemE);
    cudaFuncSetAttribute(k_post<true>,  cudaFuncAttributeMaxDynamicSharedMemorySize, (int)smemP);
    cudaFuncSetAttribute(k_post<false>, cudaFuncAttributeMaxDynamicSharedMemorySize, (int)smemP);

    k_geom<<<(E_ + 255) / 256, 256>>>(positions, edge_index, E_);
    k_prepw<<<1, 256>>>(node_embed_W, lin_up_W0,
                        prod_lin_W0, lin_up_W0 + 4096,
                        prod_lin_W1, lin_up_W1 + 4096);
    k_seed<<<(N_ * CCH + 255) / 256, 256>>>(species, N_);

    void* p0;
    void* p1;
    cudaGetSymbolAddress(&p0, d_W0c);
    cudaGetSymbolAddress(&p1, d_W1c);
    const float* W0c_sym = (const float*)p0;
    const float* W1c_sym = (const float*)p1;

    // layer 0
    k_edge<true><<<EGRID, ETHREADS, smemE>>>(edge_index, mlp_W1, mlp_W2, mlp_W3, E_);
    k_post<false><<<(N_ + 63) / 64, 256, smemP>>>(
        species, lin_W0, lin_W1, prod_W0, prod_W1,
        W0c_sym, W1c_sym, nullptr, N_);

    // layer 1
    k_edge<false><<<EGRID, ETHREADS, smemE>>>(
        edge_index, mlp_W1 + 512, mlp_W2 + 4096, mlp_W3 + 20480, E_);
    k_post<true><<<(N_ + 63) / 64, 256, smemP>>>(
        species, lin_W0 + 4096, lin_W1 + 4096,
        prod_W0 + 768, prod_W1 + 512,
        prod_lin_W0 + 4096, prod_lin_W1 + 4096,
        (float4*)d_out, N_);
}

// round 13
// speedup vs baseline: 1.4086x; 1.4086x over previous
#include <cuda_runtime.h>
#include <cstdint>

#define N_MAX 25000
#define E_MAX 400000
#define CCH 64
#define ETHREADS 512
#define EGRID 148
#define GTILE 64
#define HSTR 68

static __device__ float4 d_x[N_MAX * CCH];   // up-projected  [N][C][4]
static __device__ float4 d_M[N_MAX * CCH];   // scatter accum [N][C][4]
static __device__ float  d_ef[E_MAX * 8];    // edge bessel feats
static __device__ float4 d_Y[E_MAX];         // sqrt3 * unit vec (w unused)
static __device__ float  d_U[4 * CCH];       // embW @ lin_up_W0[0]
static __device__ float  d_W0c[CCH * CCH];   // prod_lin_W0[0] @ lin_up_W0[1]
static __device__ float  d_W1c[CCH * CCH];   // prod_lin_W1[0] @ lin_up_W1[1]

__device__ __forceinline__ float silu_f(float v) {
    return v / (1.0f + __expf(-v));
}
__device__ __forceinline__ unsigned long long pack2(float x) {
    unsigned long long r;
    asm("mov.b64 %0, {%1, %1};" : "=l"(r) : "f"(x));
    return r;
}
__device__ __forceinline__ void fma2(unsigned long long &d, unsigned long long a, unsigned long long b) {
    asm("fma.rn.f32x2 %0, %1, %2, %0;" : "+l"(d) : "l"(a), "l"(b));
}
__device__ __forceinline__ float2 unpack2(unsigned long long v) {
    float2 r;
    asm("mov.b64 {%0, %1}, %2;" : "=f"(r.x), "=f"(r.y) : "l"(v));
    return r;
}

// ---------------------------------------------------------------------------
// Per-edge geometry (accurate sinf — MUFU __sinf is NOT accurate at 8pi)
// ---------------------------------------------------------------------------
__global__ void k_geom(const float* __restrict__ pos, const int* __restrict__ ei, int E_) {
    int e = blockIdx.x * blockDim.x + threadIdx.x;
    if (e >= E_) return;
    int s = ei[e];
    int r_ = ei[E_ + e];
    float vx = pos[3*s + 0] - pos[3*r_ + 0];
    float vy = pos[3*s + 1] - pos[3*r_ + 1];
    float vz = pos[3*s + 2] - pos[3*r_ + 2];
    float rr = sqrtf(vx*vx + vy*vy + vz*vz);
    rr = fmaxf(rr, 1e-6f);
    float inv_r = 1.0f / rr;
    const float SQRT3 = 1.7320508075688772f;
    float4 Y;
    Y.x = SQRT3 * vx * inv_r;
    Y.y = SQRT3 * vy * inv_r;
    Y.z = SQRT3 * vz * inv_r;
    Y.w = 0.0f;
    d_Y[e] = Y;
    float x = rr * 0.2f;
    float x2 = x * x;
    float x6 = x2 * x2 * x2;
    float fc = 1.0f - 28.0f*x6 + 48.0f*x6*x - 21.0f*x6*x2;
    fc = (x < 1.0f) ? fc : 0.0f;
    const float BC = 0.6324555320336759f;      // sqrt(2/5)
    const float PI_O_R = 0.6283185307179586f;  // pi/5
    float pref = BC * inv_r * fc;
    float ef[8];
    #pragma unroll
    for (int k = 0; k < 8; k++)
        ef[k] = pref * sinf((float)(k + 1) * PI_O_R * rr);
    float4* dst = (float4*)(d_ef + (size_t)e * 8);
    dst[0] = make_float4(ef[0], ef[1], ef[2], ef[3]);
    dst[1] = make_float4(ef[4], ef[5], ef[6], ef[7]);
}

// ---------------------------------------------------------------------------
// Weight prep (single block)
// ---------------------------------------------------------------------------
__global__ void __launch_bounds__(256) k_prepw(
    const float* __restrict__ embW, const float* __restrict__ LU0_l0,
    const float* __restrict__ PL0_l0, const float* __restrict__ LU0_l1,
    const float* __restrict__ PL1_l0, const float* __restrict__ LU1_l1)
{
    int tid = threadIdx.x;
    {
        int s = tid >> 6, j = tid & 63;
        float acc = 0.0f;
        for (int k = 0; k < 64; k++) acc += embW[s * 64 + k] * LU0_l0[k * 64 + j];
        d_U[tid] = acc;
    }
    for (int t = tid; t < 4096; t += 256) {
        int i = t >> 6, j = t & 63;
        float a0 = 0.0f, a1 = 0.0f;
        for (int k = 0; k < 64; k++) {
            a0 += PL0_l0[i * 64 + k] * LU0_l1[k * 64 + j];
            a1 += PL1_l0[i * 64 + k] * LU1_l1[k * 64 + j];
        }
        d_W0c[t] = a0;
        d_W1c[t] = a1;
    }
}

// ---------------------------------------------------------------------------
// Layer-0 seed: x = row-select of U (h1 == 0), zero M
// ---------------------------------------------------------------------------
__global__ void k_seed(const int* __restrict__ species, int N_) {
    int idx = blockIdx.x * blockDim.x + threadIdx.x;
    if (idx >= N_ * CCH) return;
    int n = idx >> 6, c = idx & 63;
    int sp = species[n];
    d_x[idx] = make_float4(d_U[sp * CCH + c], 0.0f, 0.0f, 0.0f);
    d_M[idx] = make_float4(0, 0, 0, 0);
}

// ---------------------------------------------------------------------------
// Persistent fused edge kernel: ONE CTA of 512 threads split into TWO
// independent 8-warp groups, each on its own 64-edge tile with its own
// staging buffers + named barrier (weights shared). Independent barrier
// schedules overlap phase stalls without duplicating weight loads or
// splitting the coalesced emission.
// ---------------------------------------------------------------------------
#define SME_W1   0
#define SME_W2   512
#define SME_W3   4608
#define SME_GRP  25088
#define GRP_FL   9600    /* floats per group block */
#define SME_TOT  (SME_GRP + 2 * GRP_FL)   /* 44288 floats = 173 KB */
// group-local offsets (floats)
#define GO_EF    0
#define GO_Y     512
#define GO_SND   768
#define GO_RCV   832
#define GO_HA    896
#define GO_HB    5248

template<bool FIRST>
__device__ __forceinline__ void emit_msg(float* dst, float4 xs, float4 Yv,
                                         float t0, float t1, float t2,
                                         float t3, float t4) {
    const float INV_SQRT3 = 0.5773502691896258f;
    const float INV_SQRT2 = 0.7071067811865475f;
    float m0, m1x, m1y, m1z;
    if (FIRST) {
        m0 = t0 * xs.x;
        float a = t1 * xs.x;
        m1x = a * Yv.x;
        m1y = a * Yv.y;
        m1z = a * Yv.z;
    } else {
        float dotv = xs.y * Yv.x + xs.z * Yv.y + xs.w * Yv.z;
        m0 = t0 * xs.x + t3 * dotv * INV_SQRT3;
        float cx = xs.z * Yv.z - xs.w * Yv.y;
        float cy = xs.w * Yv.x - xs.y * Yv.z;
        float cz = xs.y * Yv.y - xs.z * Yv.x;
        float a = t1 * xs.x;
        float t4s = t4 * INV_SQRT2;
        m1x = a * Yv.x + t2 * xs.y + t4s * cx;
        m1y = a * Yv.y + t2 * xs.z + t4s * cy;
        m1z = a * Yv.z + t2 * xs.w + t4s * cz;
    }
    asm volatile("red.global.add.v4.f32 [%0], {%1,%2,%3,%4};"
                 :: "l"(dst), "f"(m0), "f"(m1x), "f"(m1y), "f"(m1z)
                 : "memory");
}

template<bool FIRST>
__global__ void __launch_bounds__(ETHREADS, 1) k_edge(
    const int* __restrict__ ei,
    const float* __restrict__ W1g, const float* __restrict__ W2g,
    const float* __restrict__ W3g, int E_)
{
    extern __shared__ float sm[];
    float* sW1 = sm + SME_W1;
    float* sW2 = sm + SME_W2;
    float* sW3 = sm + SME_W3;
    const int tid = threadIdx.x;
    const int gid = tid >> 8;          // group 0 or 1
    const int ltid = tid & 255;        // thread within group
    const int lane = tid & 31;
    const int wl = ltid >> 5;          // warp within group, 0..7
    constexpr int NB = FIRST ? 2 : 5;

    float* GB = sm + SME_GRP + gid * GRP_FL;
    float* gEF = GB + GO_EF;
    float4* gY = (float4*)(GB + GO_Y);
    int* gSnd = (int*)(GB + GO_SND);
    int* gRcv = (int*)(GB + GO_RCV);
    float* gHa = GB + GO_HA;           // [64][68]
    float* gHb = GB + GO_HB;           // [64][68]

    // shared one-time weight load
    for (int i = tid; i < 512; i += ETHREADS) sW1[i] = W1g[i];
    for (int i = tid; i < 4096; i += ETHREADS) sW2[i] = W2g[i];
    for (int i = tid; i < 20480; i += ETHREADS) sW3[i] = W3g[i];
    __syncthreads();

    const int barid = gid + 1;
    #define BARG() asm volatile("bar.sync %0, 256;" :: "r"(barid) : "memory")

    int nTiles = (E_ + GTILE - 1) / GTILE;
    for (long long t = (long long)blockIdx.x * 2 + gid; t < nTiles;
         t += (long long)EGRID * 2) {
        long long base = t * GTILE;
        BARG();    // prev tile fully consumed by this group
        if (ltid < 128) {
            long long e = base + (ltid >> 1);
            float4 v = make_float4(0, 0, 0, 0);
            if (e < E_) v = ((const float4*)d_ef)[e * 2 + (ltid & 1)];
            ((float4*)gEF)[ltid] = v;
        } else if (ltid < 192) {
            int i = ltid - 128;
            long long e = base + i;
            float4 y = make_float4(0, 0, 0, 0);
            if (e < E_) y = d_Y[e];
            gY[i] = y;
        } else {
            int i = ltid - 192;
            long long e = base + i;
            int s = 0, r = -1;
            if (e < E_) { s = ei[e]; r = ei[E_ + e]; }
            gSnd[i] = s;
            gRcv[i] = r;
        }
        BARG();

        // Phase B: H1 = silu(EF @ W1)  [64x8]@[8x64], 16 outputs/thread
        #pragma unroll
        for (int i = 0; i < 16; i++) {
            int idx = ltid + 256 * i;
            int e = idx >> 6, j = idx & 63;
            float acc = 0.0f;
            #pragma unroll
            for (int k = 0; k < 8; k++) acc += gEF[e * 8 + k] * sW1[k * 64 + j];
            gHa[e * HSTR + j] = silu_f(acc);
        }
        BARG();

        // Phase C: H2 = silu(H1 @ W2)  [64x64]@[64x64], 4 edges x 4 cols,
        // float2 K-batched a-broadcasts.
        {
            int e0 = (ltid >> 4) << 2;
            int j0 = (ltid & 15) << 2;
            unsigned long long acc[4][2] = {};
            #pragma unroll 2
            for (int cc = 0; cc < 64; cc += 2) {
                float2 a[4];
                #pragma unroll
                for (int i = 0; i < 4; i++)
                    a[i] = *(const float2*)&gHa[(e0 + i) * HSTR + cc];
                #pragma unroll
                for (int k = 0; k < 2; k++) {
                    const unsigned long long* bp =
                        (const unsigned long long*)&sW2[(cc + k) * 64 + j0];
                    unsigned long long b0 = bp[0], b1 = bp[1];
                    #pragma unroll
                    for (int i = 0; i < 4; i++) {
                        unsigned long long a2 = pack2(k ? a[i].y : a[i].x);
                        fma2(acc[i][0], a2, b0);
                        fma2(acc[i][1], a2, b1);
                    }
                }
            }
            #pragma unroll
            for (int i = 0; i < 4; i++) {
                float2 p0 = unpack2(acc[i][0]);
                float2 p1 = unpack2(acc[i][1]);
                float* dst = &gHb[(e0 + i) * HSTR + j0];
                dst[0] = silu_f(p0.x);
                dst[1] = silu_f(p0.y);
                dst[2] = silu_f(p1.x);
                dst[3] = silu_f(p1.y);
            }
        }
        BARG();

        // Phase D+E fused: warp wl owns edges 8wl..8wl+7; thread owns one
        // channel pair (cb). acc = 8 x NB u64 (<=80 regs, no spill @128 cap).
        {
            int eb = wl * 8;
            int cb = lane * 2;
            unsigned long long acc[8][NB];
            #pragma unroll
            for (int ii = 0; ii < 8; ii++)
                #pragma unroll
                for (int p = 0; p < NB; p++) acc[ii][p] = 0ull;

            #pragma unroll 2
            for (int cc = 0; cc < 64; cc++) {
                const float* wrow = &sW3[cc * 320 + cb];
                unsigned long long b[NB];
                #pragma unroll
                for (int p = 0; p < NB; p++)
                    b[p] = *(const unsigned long long*)(wrow + 64 * p);
                #pragma unroll
                for (int ii = 0; ii < 8; ii++) {
                    unsigned long long a2 = pack2(gHb[(eb + ii) * HSTR + cc]);
                    #pragma unroll
                    for (int p = 0; p < NB; p++) fma2(acc[ii][p], a2, b[p]);
                }
            }

            // emission: per edge, coalesced full-warp gather + red.v4
            #pragma unroll 1
            for (int ii = 0; ii < 8; ii++) {
                int el = eb + ii;
                int r = gRcv[el];
                if (r < 0) continue;
                int s = gSnd[el];
                float4 Yv = gY[el];
                const float4* xp = &d_x[(size_t)s * CCH + cb];
                float4 xs0 = xp[0];
                float4 xs1 = xp[1];
                float2 t0 = unpack2(acc[ii][0]);
                float2 t1 = unpack2(acc[ii][1]);
                float2 t2 = make_float2(0, 0), t3 = make_float2(0, 0), t4 = make_float2(0, 0);
                if (!FIRST) {
                    t2 = unpack2(acc[ii][2]);
                    t3 = unpack2(acc[ii][3]);
                    t4 = unpack2(acc[ii][4]);
                }
                float* dst = (float*)&d_M[(size_t)r * CCH + cb];
                emit_msg<FIRST>(dst,     xs0, Yv, t0.x, t1.x, t2.x, t3.x, t4.x);
                emit_msg<FIRST>(dst + 4, xs1, Yv, t0.y, t1.y, t2.y, t3.y, t4.y);
            }
        }
    }
    #undef BARG
}

// ---------------------------------------------------------------------------
// Fused post(l0)+up(l1) / final post
// ---------------------------------------------------------------------------
#define SMP_LW0 0
#define SMP_LW1 4096
#define SMP_PL0 8192
#define SMP_PL1 12288
#define SMP_PW0 16384
#define SMP_PW1 17152
#define SMP_A   17664
#define SMP_B   18688
#define SMP_TOT 19712   // floats

template<bool FINAL>
__global__ void __launch_bounds__(256) k_post(
    const int* __restrict__ species,
    const float* __restrict__ LW0g, const float* __restrict__ LW1g,
    const float* __restrict__ PW0g, const float* __restrict__ PW1g,
    const float* __restrict__ PL0g, const float* __restrict__ PL1g,
    float4* __restrict__ out, int N_)
{
    extern __shared__ float sm[];
    float* sLW0 = sm + SMP_LW0;
    float* sLW1 = sm + SMP_LW1;
    float* sPL0 = sm + SMP_PL0;
    float* sPL1 = sm + SMP_PL1;
    float* sPW0 = sm + SMP_PW0;
    float* sPW1 = sm + SMP_PW1;
    float4* sA = (float4*)(sm + SMP_A);
    float4* sB = (float4*)(sm + SMP_B);
    int tid = threadIdx.x;
    const float INV_SQRT3 = 0.5773502691896258f;
    for (int i = tid; i < 4096; i += 256) {
        sLW0[i] = LW0g[i];
        sLW1[i] = LW1g[i];
        sPL0[i] = PL0g[i];
        sPL1[i] = PL1g[i];
    }
    for (int i = tid; i < 768; i += 256) sPW0[i] = PW0g[i];
    for (int i = tid; i < 512; i += 256) sPW1[i] = PW1g[i];
    __syncthreads();

    int base = blockIdx.x * 64;
    int c = tid & 63, sub = tid >> 6;
    for (int g = 0; g < 16; g++) {
        int n = base + g * 4 + sub;
        bool act = n < N_;
        if (act) {
            float4 mv = d_M[(size_t)n * CCH + c];
            mv.x *= 0.0625f; mv.y *= 0.0625f; mv.z *= 0.0625f; mv.w *= 0.0625f;
            sA[sub * CCH + c] = mv;
        }
        __syncthreads();
        if (act) {
            float h0 = 0, h1x = 0, h1y = 0, h1z = 0;
            const float4* ar = &sA[sub * CCH];
            #pragma unroll 8
            for (int cc = 0; cc < 64; cc++) {
                float4 a = ar[cc];
                float w0 = sLW0[cc * 64 + c];
                float w1 = sLW1[cc * 64 + c];
                h0 += a.x * w0;
                h1x += a.y * w1;
                h1y += a.z * w1;
                h1z += a.w * w1;
            }
            int sp = species[n];
            float nrm = (h1x * h1x + h1y * h1y + h1z * h1z) * INV_SQRT3;
            const float* p0 = &sPW0[sp * 192 + c];
            float b0 = p0[0] * h0 + p0[64] * h0 * h0 + p0[128] * nrm;
            const float* p1 = &sPW1[sp * 128 + c];
            float q = p1[0] + p1[64] * h0;
            sB[sub * CCH + c] = make_float4(b0, q * h1x, q * h1y, q * h1z);
        }
        __syncthreads();
        if (act) {
            float o0 = 0, o1 = 0, o2 = 0, o3 = 0;
            const float4* br = &sB[sub * CCH];
            #pragma unroll 8
            for (int cc = 0; cc < 64; cc++) {
                float4 b = br[cc];
                float w0 = sPL0[cc * 64 + c];
                float w1 = sPL1[cc * 64 + c];
                o0 += b.x * w0;
                o1 += b.y * w1;
                o2 += b.z * w1;
                o3 += b.w * w1;
            }
            if (FINAL) {
                out[(size_t)n * CCH + c] = make_float4(o0, o1, o2, o3);
            } else {
                d_x[(size_t)n * CCH + c] = make_float4(o0, o1, o2, o3);
                d_M[(size_t)n * CCH + c] = make_float4(0, 0, 0, 0);
            }
        }
        __syncthreads();
    }
}

// ---------------------------------------------------------------------------
extern "C" void kernel_launch(void* const* d_in, const int* in_sizes, int n_in,
                              void* d_out, int out_size) {
    const float* positions    = (const float*)d_in[0];
    const int*   species      = (const int*)d_in[1];
    const int*   edge_index   = (const int*)d_in[2];
    const float* node_embed_W = (const float*)d_in[3];
    const float* lin_up_W0    = (const float*)d_in[4];
    const float* lin_up_W1    = (const float*)d_in[5];
    const float* mlp_W1       = (const float*)d_in[6];
    const float* mlp_W2       = (const float*)d_in[7];
    const float* mlp_W3       = (const float*)d_in[8];
    const float* lin_W0       = (const float*)d_in[9];
    const float* lin_W1       = (const float*)d_in[10];
    const float* prod_W0      = (const float*)d_in[11];
    const float* prod_W1      = (const float*)d_in[12];
    const float* prod_lin_W0  = (const float*)d_in[13];
    const float* prod_lin_W1  = (const float*)d_in[14];

    int N_ = in_sizes[0] / 3;
    int E_ = in_sizes[2] / 2;

    size_t smemE = (size_t)SME_TOT * 4;
    size_t smemP = (size_t)SMP_TOT * 4;
    cudaFuncSetAttribute(k_edge<true>,  cudaFuncAttributeMaxDynamicSharedMemorySize, (int)smemE);
    cudaFuncSetAttribute(k_edge<false>, cudaFuncAttributeMaxDynamicSharedMemorySize, (int)smemE);
    cudaFuncSetAttribute(k_post<true>,  cudaFuncAttributeMaxDynamicSharedMemorySize, (int)smemP);
    cudaFuncSetAttribute(k_post<false>, cudaFuncAttributeMaxDynamicSharedMemorySize, (int)smemP);

    k_geom<<<(E_ + 255) / 256, 256>>>(positions, edge_index, E_);
    k_prepw<<<1, 256>>>(node_embed_W, lin_up_W0,
                        prod_lin_W0, lin_up_W0 + 4096,
                        prod_lin_W1, lin_up_W1 + 4096);
    k_seed<<<(N_ * CCH + 255) / 256, 256>>>(species, N_);

    void* p0;
    void* p1;
    cudaGetSymbolAddress(&p0, d_W0c);
    cudaGetSymbolAddress(&p1, d_W1c);
    const float* W0c_sym = (const float*)p0;
    const float* W1c_sym = (const float*)p1;

    // layer 0
    k_edge<true><<<EGRID, ETHREADS, smemE>>>(edge_index, mlp_W1, mlp_W2, mlp_W3, E_);
    k_post<false><<<(N_ + 63) / 64, 256, smemP>>>(
        species, lin_W0, lin_W1, prod_W0, prod_W1,
        W0c_sym, W1c_sym, nullptr, N_);

    // layer 1
    k_edge<false><<<EGRID, ETHREADS, smemE>>>(
        edge_index, mlp_W1 + 512, mlp_W2 + 4096, mlp_W3 + 20480, E_);
    k_post<true><<<(N_ + 63) / 64, 256, smemP>>>(
        species, lin_W0 + 4096, lin_W1 + 4096,
        prod_W0 + 768, prod_W1 + 512,
        prod_lin_W0 + 4096, prod_lin_W1 + 4096,
        (float4*)d_out, N_);
}

// round 14
// speedup vs baseline: 1.4088x; 1.0001x over previous
#include <cuda_runtime.h>
#include <cstdint>

#define N_MAX 25000
#define E_MAX 400000
#define CCH 64
#define ETHREADS 512
#define EGRID 148
#define GTILE 64
#define HSTR 68

static __device__ float4 d_x[N_MAX * CCH];   // up-projected  [N][C][4]
static __device__ float4 d_M[N_MAX * CCH];   // scatter accum [N][C][4]
static __device__ float  d_ef[E_MAX * 8];    // edge bessel feats
static __device__ float4 d_Y[E_MAX];         // sqrt3 * unit vec (w unused)
static __device__ float  d_U[4 * CCH];       // embW @ lin_up_W0[0]
static __device__ float  d_W0c[CCH * CCH];   // prod_lin_W0[0] @ lin_up_W0[1]
static __device__ float  d_W1c[CCH * CCH];   // prod_lin_W1[0] @ lin_up_W1[1]

__device__ __forceinline__ float silu_f(float v) {
    return v / (1.0f + __expf(-v));
}
__device__ __forceinline__ unsigned long long pack2(float x) {
    unsigned long long r;
    asm("mov.b64 %0, {%1, %1};" : "=l"(r) : "f"(x));
    return r;
}
__device__ __forceinline__ void fma2(unsigned long long &d, unsigned long long a, unsigned long long b) {
    asm("fma.rn.f32x2 %0, %1, %2, %0;" : "+l"(d) : "l"(a), "l"(b));
}
__device__ __forceinline__ float2 unpack2(unsigned long long v) {
    float2 r;
    asm("mov.b64 {%0, %1}, %2;" : "=f"(r.x), "=f"(r.y) : "l"(v));
    return r;
}

// ---------------------------------------------------------------------------
// Per-edge geometry: ONE accurate sincosf + exact angle-addition recurrence
// for the 8 bessel harmonics (replaces 8 slow sinf calls).
// ---------------------------------------------------------------------------
__global__ void k_geom(const float* __restrict__ pos, const int* __restrict__ ei, int E_) {
    int e = blockIdx.x * blockDim.x + threadIdx.x;
    if (e >= E_) return;
    int s = ei[e];
    int r_ = ei[E_ + e];
    float vx = pos[3*s + 0] - pos[3*r_ + 0];
    float vy = pos[3*s + 1] - pos[3*r_ + 1];
    float vz = pos[3*s + 2] - pos[3*r_ + 2];
    float rr = sqrtf(vx*vx + vy*vy + vz*vz);
    rr = fmaxf(rr, 1e-6f);
    float inv_r = 1.0f / rr;
    const float SQRT3 = 1.7320508075688772f;
    float4 Y;
    Y.x = SQRT3 * vx * inv_r;
    Y.y = SQRT3 * vy * inv_r;
    Y.z = SQRT3 * vz * inv_r;
    Y.w = 0.0f;
    d_Y[e] = Y;
    float x = rr * 0.2f;
    float x2 = x * x;
    float x6 = x2 * x2 * x2;
    float fc = 1.0f - 28.0f*x6 + 48.0f*x6*x - 21.0f*x6*x2;
    fc = (x < 1.0f) ? fc : 0.0f;
    const float BC = 0.6324555320336759f;      // sqrt(2/5)
    const float PI_O_R = 0.6283185307179586f;  // pi/5
    float pref = BC * inv_r * fc;
    float theta = PI_O_R * rr;
    float s1, c1;
    sincosf(theta, &s1, &c1);
    float ef[8];
    float sk = s1, ck = c1;
    ef[0] = pref * sk;
    #pragma unroll
    for (int k = 1; k < 8; k++) {
        float sn = sk * c1 + ck * s1;   // sin((k+1)theta)
        float cn = ck * c1 - sk * s1;   // cos((k+1)theta)
        sk = sn; ck = cn;
        ef[k] = pref * sk;
    }
    float4* dst = (float4*)(d_ef + (size_t)e * 8);
    dst[0] = make_float4(ef[0], ef[1], ef[2], ef[3]);
    dst[1] = make_float4(ef[4], ef[5], ef[6], ef[7]);
}

// ---------------------------------------------------------------------------
// Weight prep (17 blocks: 0..15 do W0c/W1c slices, 16 does U)
// ---------------------------------------------------------------------------
__global__ void __launch_bounds__(256) k_prepw(
    const float* __restrict__ embW, const float* __restrict__ LU0_l0,
    const float* __restrict__ PL0_l0, const float* __restrict__ LU0_l1,
    const float* __restrict__ PL1_l0, const float* __restrict__ LU1_l1)
{
    int tid = threadIdx.x;
    int b = blockIdx.x;
    if (b == 16) {
        int s = tid >> 6, j = tid & 63;
        float acc = 0.0f;
        for (int k = 0; k < 64; k++) acc += embW[s * 64 + k] * LU0_l0[k * 64 + j];
        d_U[tid] = acc;
        return;
    }
    int t = b * 256 + tid;
    int i = t >> 6, j = t & 63;
    float a0 = 0.0f, a1 = 0.0f;
    for (int k = 0; k < 64; k++) {
        a0 += PL0_l0[i * 64 + k] * LU0_l1[k * 64 + j];
        a1 += PL1_l0[i * 64 + k] * LU1_l1[k * 64 + j];
    }
    d_W0c[t] = a0;
    d_W1c[t] = a1;
}

// ---------------------------------------------------------------------------
// Layer-0 seed: x = row-select of U (h1 == 0), zero M
// ---------------------------------------------------------------------------
__global__ void k_seed(const int* __restrict__ species, int N_) {
    int idx = blockIdx.x * blockDim.x + threadIdx.x;
    if (idx >= N_ * CCH) return;
    int n = idx >> 6, c = idx & 63;
    int sp = species[n];
    d_x[idx] = make_float4(d_U[sp * CCH + c], 0.0f, 0.0f, 0.0f);
    d_M[idx] = make_float4(0, 0, 0, 0);
}

// ---------------------------------------------------------------------------
// Persistent fused edge kernel: ONE CTA of 512 threads, TWO independent
// 8-warp groups (named barriers), shared weights, per-group 64-edge tiles.
// Phase D uses float2 K-batched a-broadcasts (halves a-wavefronts).
// ---------------------------------------------------------------------------
#define SME_W1   0
#define SME_W2   512
#define SME_W3   4608
#define SME_GRP  25088
#define GRP_FL   9600    /* floats per group block */
#define SME_TOT  (SME_GRP + 2 * GRP_FL)   /* 44288 floats = 173 KB */
// group-local offsets (floats)
#define GO_EF    0
#define GO_Y     512
#define GO_SND   768
#define GO_RCV   832
#define GO_HA    896
#define GO_HB    5248

template<bool FIRST>
__device__ __forceinline__ void emit_msg(float* dst, float4 xs, float4 Yv,
                                         float t0, float t1, float t2,
                                         float t3, float t4) {
    const float INV_SQRT3 = 0.5773502691896258f;
    const float INV_SQRT2 = 0.7071067811865475f;
    float m0, m1x, m1y, m1z;
    if (FIRST) {
        m0 = t0 * xs.x;
        float a = t1 * xs.x;
        m1x = a * Yv.x;
        m1y = a * Yv.y;
        m1z = a * Yv.z;
    } else {
        float dotv = xs.y * Yv.x + xs.z * Yv.y + xs.w * Yv.z;
        m0 = t0 * xs.x + t3 * dotv * INV_SQRT3;
        float cx = xs.z * Yv.z - xs.w * Yv.y;
        float cy = xs.w * Yv.x - xs.y * Yv.z;
        float cz = xs.y * Yv.y - xs.z * Yv.x;
        float a = t1 * xs.x;
        float t4s = t4 * INV_SQRT2;
        m1x = a * Yv.x + t2 * xs.y + t4s * cx;
        m1y = a * Yv.y + t2 * xs.z + t4s * cy;
        m1z = a * Yv.z + t2 * xs.w + t4s * cz;
    }
    asm volatile("red.global.add.v4.f32 [%0], {%1,%2,%3,%4};"
                 :: "l"(dst), "f"(m0), "f"(m1x), "f"(m1y), "f"(m1z)
                 : "memory");
}

template<bool FIRST>
__global__ void __launch_bounds__(ETHREADS, 1) k_edge(
    const int* __restrict__ ei,
    const float* __restrict__ W1g, const float* __restrict__ W2g,
    const float* __restrict__ W3g, int E_)
{
    extern __shared__ float sm[];
    float* sW1 = sm + SME_W1;
    float* sW2 = sm + SME_W2;
    float* sW3 = sm + SME_W3;
    const int tid = threadIdx.x;
    const int gid = tid >> 8;          // group 0 or 1
    const int ltid = tid & 255;        // thread within group
    const int lane = tid & 31;
    const int wl = ltid >> 5;          // warp within group, 0..7
    constexpr int NB = FIRST ? 2 : 5;

    float* GB = sm + SME_GRP + gid * GRP_FL;
    float* gEF = GB + GO_EF;
    float4* gY = (float4*)(GB + GO_Y);
    int* gSnd = (int*)(GB + GO_SND);
    int* gRcv = (int*)(GB + GO_RCV);
    float* gHa = GB + GO_HA;           // [64][68]
    float* gHb = GB + GO_HB;           // [64][68]

    // shared one-time weight load
    for (int i = tid; i < 512; i += ETHREADS) sW1[i] = W1g[i];
    for (int i = tid; i < 4096; i += ETHREADS) sW2[i] = W2g[i];
    for (int i = tid; i < 20480; i += ETHREADS) sW3[i] = W3g[i];
    __syncthreads();

    const int barid = gid + 1;
    #define BARG() asm volatile("bar.sync %0, 256;" :: "r"(barid) : "memory")

    int nTiles = (E_ + GTILE - 1) / GTILE;
    for (long long t = (long long)blockIdx.x * 2 + gid; t < nTiles;
         t += (long long)EGRID * 2) {
        long long base = t * GTILE;
        BARG();    // prev tile fully consumed by this group
        if (ltid < 128) {
            long long e = base + (ltid >> 1);
            float4 v = make_float4(0, 0, 0, 0);
            if (e < E_) v = ((const float4*)d_ef)[e * 2 + (ltid & 1)];
            ((float4*)gEF)[ltid] = v;
        } else if (ltid < 192) {
            int i = ltid - 128;
            long long e = base + i;
            float4 y = make_float4(0, 0, 0, 0);
            if (e < E_) y = d_Y[e];
            gY[i] = y;
        } else {
            int i = ltid - 192;
            long long e = base + i;
            int s = 0, r = -1;
            if (e < E_) { s = ei[e]; r = ei[E_ + e]; }
            gSnd[i] = s;
            gRcv[i] = r;
        }
        BARG();

        // Phase B: H1 = silu(EF @ W1)  [64x8]@[8x64], 16 outputs/thread
        #pragma unroll
        for (int i = 0; i < 16; i++) {
            int idx = ltid + 256 * i;
            int e = idx >> 6, j = idx & 63;
            float acc = 0.0f;
            #pragma unroll
            for (int k = 0; k < 8; k++) acc += gEF[e * 8 + k] * sW1[k * 64 + j];
            gHa[e * HSTR + j] = silu_f(acc);
        }
        BARG();

        // Phase C: H2 = silu(H1 @ W2)  [64x64]@[64x64], 4 edges x 4 cols,
        // float2 K-batched a-broadcasts.
        {
            int e0 = (ltid >> 4) << 2;
            int j0 = (ltid & 15) << 2;
            unsigned long long acc[4][2] = {};
            #pragma unroll 2
            for (int cc = 0; cc < 64; cc += 2) {
                float2 a[4];
                #pragma unroll
                for (int i = 0; i < 4; i++)
                    a[i] = *(const float2*)&gHa[(e0 + i) * HSTR + cc];
                #pragma unroll
                for (int k = 0; k < 2; k++) {
                    const unsigned long long* bp =
                        (const unsigned long long*)&sW2[(cc + k) * 64 + j0];
                    unsigned long long b0 = bp[0], b1 = bp[1];
                    #pragma unroll
                    for (int i = 0; i < 4; i++) {
                        unsigned long long a2 = pack2(k ? a[i].y : a[i].x);
                        fma2(acc[i][0], a2, b0);
                        fma2(acc[i][1], a2, b1);
                    }
                }
            }
            #pragma unroll
            for (int i = 0; i < 4; i++) {
                float2 p0 = unpack2(acc[i][0]);
                float2 p1 = unpack2(acc[i][1]);
                float* dst = &gHb[(e0 + i) * HSTR + j0];
                dst[0] = silu_f(p0.x);
                dst[1] = silu_f(p0.y);
                dst[2] = silu_f(p1.x);
                dst[3] = silu_f(p1.y);
            }
        }
        BARG();

        // Phase D+E fused: warp wl owns edges 8wl..8wl+7; thread owns one
        // channel pair. float2 K-batched a-broadcasts (halves a-wavefronts).
        {
            int eb = wl * 8;
            int cb = lane * 2;
            unsigned long long acc[8][NB];
            #pragma unroll
            for (int ii = 0; ii < 8; ii++)
                #pragma unroll
                for (int p = 0; p < NB; p++) acc[ii][p] = 0ull;

            #pragma unroll 1
            for (int cc = 0; cc < 64; cc += 2) {
                float2 a[8];
                #pragma unroll
                for (int ii = 0; ii < 8; ii++)
                    a[ii] = *(const float2*)&gHb[(eb + ii) * HSTR + cc];
                #pragma unroll
                for (int k = 0; k < 2; k++) {
                    const float* wrow = &sW3[(cc + k) * 320 + cb];
                    unsigned long long b[NB];
                    #pragma unroll
                    for (int p = 0; p < NB; p++)
                        b[p] = *(const unsigned long long*)(wrow + 64 * p);
                    #pragma unroll
                    for (int ii = 0; ii < 8; ii++) {
                        unsigned long long a2 = pack2(k ? a[ii].y : a[ii].x);
                        #pragma unroll
                        for (int p = 0; p < NB; p++) fma2(acc[ii][p], a2, b[p]);
                    }
                }
            }

            // emission: per edge, coalesced full-warp gather + red.v4
            #pragma unroll 1
            for (int ii = 0; ii < 8; ii++) {
                int el = eb + ii;
                int r = gRcv[el];
                if (r < 0) continue;
                int s = gSnd[el];
                float4 Yv = gY[el];
                const float4* xp = &d_x[(size_t)s * CCH + cb];
                float4 xs0 = xp[0];
                float4 xs1 = xp[1];
                float2 t0 = unpack2(acc[ii][0]);
                float2 t1 = unpack2(acc[ii][1]);
                float2 t2 = make_float2(0, 0), t3 = make_float2(0, 0), t4 = make_float2(0, 0);
                if (!FIRST) {
                    t2 = unpack2(acc[ii][2]);
                    t3 = unpack2(acc[ii][3]);
                    t4 = unpack2(acc[ii][4]);
                }
                float* dst = (float*)&d_M[(size_t)r * CCH + cb];
                emit_msg<FIRST>(dst,     xs0, Yv, t0.x, t1.x, t2.x, t3.x, t4.x);
                emit_msg<FIRST>(dst + 4, xs1, Yv, t0.y, t1.y, t2.y, t3.y, t4.y);
            }
        }
    }
    #undef BARG
}

// ---------------------------------------------------------------------------
// Fused post(l0)+up(l1) / final post
// ---------------------------------------------------------------------------
#define SMP_LW0 0
#define SMP_LW1 4096
#define SMP_PL0 8192
#define SMP_PL1 12288
#define SMP_PW0 16384
#define SMP_PW1 17152
#define SMP_A   17664
#define SMP_B   18688
#define SMP_TOT 19712   // floats

template<bool FINAL>
__global__ void __launch_bounds__(256) k_post(
    const int* __restrict__ species,
    const float* __restrict__ LW0g, const float* __restrict__ LW1g,
    const float* __restrict__ PW0g, const float* __restrict__ PW1g,
    const float* __restrict__ PL0g, const float* __restrict__ PL1g,
    float4* __restrict__ out, int N_)
{
    extern __shared__ float sm[];
    float* sLW0 = sm + SMP_LW0;
    float* sLW1 = sm + SMP_LW1;
    float* sPL0 = sm + SMP_PL0;
    float* sPL1 = sm + SMP_PL1;
    float* sPW0 = sm + SMP_PW0;
    float* sPW1 = sm + SMP_PW1;
    float4* sA = (float4*)(sm + SMP_A);
    float4* sB = (float4*)(sm + SMP_B);
    int tid = threadIdx.x;
    const float INV_SQRT3 = 0.5773502691896258f;
    for (int i = tid; i < 4096; i += 256) {
        sLW0[i] = LW0g[i];
        sLW1[i] = LW1g[i];
        sPL0[i] = PL0g[i];
        sPL1[i] = PL1g[i];
    }
    for (int i = tid; i < 768; i += 256) sPW0[i] = PW0g[i];
    for (int i = tid; i < 512; i += 256) sPW1[i] = PW1g[i];
    __syncthreads();

    int base = blockIdx.x * 64;
    int c = tid & 63, sub = tid >> 6;
    for (int g = 0; g < 16; g++) {
        int n = base + g * 4 + sub;
        bool act = n < N_;
        if (act) {
            float4 mv = d_M[(size_t)n * CCH + c];
            mv.x *= 0.0625f; mv.y *= 0.0625f; mv.z *= 0.0625f; mv.w *= 0.0625f;
            sA[sub * CCH + c] = mv;
        }
        __syncthreads();
        if (act) {
            float h0 = 0, h1x = 0, h1y = 0, h1z = 0;
            const float4* ar = &sA[sub * CCH];
            #pragma unroll 8
            for (int cc = 0; cc < 64; cc++) {
                float4 a = ar[cc];
                float w0 = sLW0[cc * 64 + c];
                float w1 = sLW1[cc * 64 + c];
                h0 += a.x * w0;
                h1x += a.y * w1;
                h1y += a.z * w1;
                h1z += a.w * w1;
            }
            int sp = species[n];
            float nrm = (h1x * h1x + h1y * h1y + h1z * h1z) * INV_SQRT3;
            const float* p0 = &sPW0[sp * 192 + c];
            float b0 = p0[0] * h0 + p0[64] * h0 * h0 + p0[128] * nrm;
            const float* p1 = &sPW1[sp * 128 + c];
            float q = p1[0] + p1[64] * h0;
            sB[sub * CCH + c] = make_float4(b0, q * h1x, q * h1y, q * h1z);
        }
        __syncthreads();
        if (act) {
            float o0 = 0, o1 = 0, o2 = 0, o3 = 0;
            const float4* br = &sB[sub * CCH];
            #pragma unroll 8
            for (int cc = 0; cc < 64; cc++) {
                float4 b = br[cc];
                float w0 = sPL0[cc * 64 + c];
                float w1 = sPL1[cc * 64 + c];
                o0 += b.x * w0;
                o1 += b.y * w1;
                o2 += b.z * w1;
                o3 += b.w * w1;
            }
            if (FINAL) {
                out[(size_t)n * CCH + c] = make_float4(o0, o1, o2, o3);
            } else {
                d_x[(size_t)n * CCH + c] = make_float4(o0, o1, o2, o3);
                d_M[(size_t)n * CCH + c] = make_float4(0, 0, 0, 0);
            }
        }
        __syncthreads();
    }
}

// ---------------------------------------------------------------------------
extern "C" void kernel_launch(void* const* d_in, const int* in_sizes, int n_in,
                              void* d_out, int out_size) {
    const float* positions    = (const float*)d_in[0];
    const int*   species      = (const int*)d_in[1];
    const int*   edge_index   = (const int*)d_in[2];
    const float* node_embed_W = (const float*)d_in[3];
    const float* lin_up_W0    = (const float*)d_in[4];
    const float* lin_up_W1    = (const float*)d_in[5];
    const float* mlp_W1       = (const float*)d_in[6];
    const float* mlp_W2       = (const float*)d_in[7];
    const float* mlp_W3       = (const float*)d_in[8];
    const float* lin_W0       = (const float*)d_in[9];
    const float* lin_W1       = (const float*)d_in[10];
    const float* prod_W0      = (const float*)d_in[11];
    const float* prod_W1      = (const float*)d_in[12];
    const float* prod_lin_W0  = (const float*)d_in[13];
    const float* prod_lin_W1  = (const float*)d_in[14];

    int N_ = in_sizes[0] / 3;
    int E_ = in_sizes[2] / 2;

    size_t smemE = (size_t)SME_TOT * 4;
    size_t smemP = (size_t)SMP_TOT * 4;
    cudaFuncSetAttribute(k_edge<true>,  cudaFuncAttributeMaxDynamicSharedMemorySize, (int)smemE);
    cudaFuncSetAttribute(k_edge<false>, cudaFuncAttributeMaxDynamicSharedMemorySize, (int)smemE);
    cudaFuncSetAttribute(k_post<true>,  cudaFuncAttributeMaxDynamicSharedMemorySize, (int)smemP);
    cudaFuncSetAttribute(k_post<false>, cudaFuncAttributeMaxDynamicSharedMemorySize, (int)smemP);

    k_geom<<<(E_ + 255) / 256, 256>>>(positions, edge_index, E_);
    k_prepw<<<17, 256>>>(node_embed_W, lin_up_W0,
                         prod_lin_W0, lin_up_W0 + 4096,
                         prod_lin_W1, lin_up_W1 + 4096);
    k_seed<<<(N_ * CCH + 255) / 256, 256>>>(species, N_);

    void* p0;
    void* p1;
    cudaGetSymbolAddress(&p0, d_W0c);
    cudaGetSymbolAddress(&p1, d_W1c);
    const float* W0c_sym = (const float*)p0;
    const float* W1c_sym = (const float*)p1;

    // layer 0
    k_edge<true><<<EGRID, ETHREADS, smemE>>>(edge_index, mlp_W1, mlp_W2, mlp_W3, E_);
    k_post<false><<<(N_ + 63) / 64, 256, smemP>>>(
        species, lin_W0, lin_W1, prod_W0, prod_W1,
        W0c_sym, W1c_sym, nullptr, N_);

    // layer 1
    k_edge<false><<<EGRID, ETHREADS, smemE>>>(
        edge_index, mlp_W1 + 512, mlp_W2 + 4096, mlp_W3 + 20480, E_);
    k_post<true><<<(N_ + 63) / 64, 256, smemP>>>(
        species, lin_W0 + 4096, lin_W1 + 4096,
        prod_W0 + 768, prod_W1 + 512,
        prod_lin_W0 + 4096, prod_lin_W1 + 4096,
        (float4*)d_out, N_);
}

// round 15
// speedup vs baseline: 1.4522x; 1.0308x over previous
#include <cuda_runtime.h>
#include <cstdint>

#define N_MAX 25000
#define E_MAX 400000
#define CCH 64
#define ETHREADS 512
#define EGRID 148
#define GTILE 64
#define HSTR 68

static __device__ float4 d_x[N_MAX * CCH];   // up-projected  [N][C][4]
static __device__ float4 d_M[N_MAX * CCH];   // scatter accum [N][C][4]
static __device__ float  d_ef[E_MAX * 8];    // edge bessel feats
static __device__ float4 d_Y[E_MAX];         // sqrt3 * unit vec (w unused)
static __device__ float  d_U[4 * CCH];       // embW @ lin_up_W0[0]
static __device__ float  d_W0c[CCH * CCH];   // prod_lin_W0[0] @ lin_up_W0[1]
static __device__ float  d_W1c[CCH * CCH];   // prod_lin_W1[0] @ lin_up_W1[1]

__device__ __forceinline__ float silu_f(float v) {
    return v / (1.0f + __expf(-v));
}
__device__ __forceinline__ unsigned long long pack2(float x) {
    unsigned long long r;
    asm("mov.b64 %0, {%1, %1};" : "=l"(r) : "f"(x));
    return r;
}
__device__ __forceinline__ void fma2(unsigned long long &d, unsigned long long a, unsigned long long b) {
    asm("fma.rn.f32x2 %0, %1, %2, %0;" : "+l"(d) : "l"(a), "l"(b));
}
__device__ __forceinline__ float2 unpack2(unsigned long long v) {
    float2 r;
    asm("mov.b64 {%0, %1}, %2;" : "=f"(r.x), "=f"(r.y) : "l"(v));
    return r;
}

// ---------------------------------------------------------------------------
// Per-edge geometry: one sincosf + exact angle-addition recurrence
// ---------------------------------------------------------------------------
__global__ void k_geom(const float* __restrict__ pos, const int* __restrict__ ei, int E_) {
    int e = blockIdx.x * blockDim.x + threadIdx.x;
    if (e >= E_) return;
    int s = ei[e];
    int r_ = ei[E_ + e];
    float vx = pos[3*s + 0] - pos[3*r_ + 0];
    float vy = pos[3*s + 1] - pos[3*r_ + 1];
    float vz = pos[3*s + 2] - pos[3*r_ + 2];
    float rr = sqrtf(vx*vx + vy*vy + vz*vz);
    rr = fmaxf(rr, 1e-6f);
    float inv_r = 1.0f / rr;
    const float SQRT3 = 1.7320508075688772f;
    float4 Y;
    Y.x = SQRT3 * vx * inv_r;
    Y.y = SQRT3 * vy * inv_r;
    Y.z = SQRT3 * vz * inv_r;
    Y.w = 0.0f;
    d_Y[e] = Y;
    float x = rr * 0.2f;
    float x2 = x * x;
    float x6 = x2 * x2 * x2;
    float fc = 1.0f - 28.0f*x6 + 48.0f*x6*x - 21.0f*x6*x2;
    fc = (x < 1.0f) ? fc : 0.0f;
    const float BC = 0.6324555320336759f;      // sqrt(2/5)
    const float PI_O_R = 0.6283185307179586f;  // pi/5
    float pref = BC * inv_r * fc;
    float theta = PI_O_R * rr;
    float s1, c1;
    sincosf(theta, &s1, &c1);
    float ef[8];
    float sk = s1, ck = c1;
    ef[0] = pref * sk;
    #pragma unroll
    for (int k = 1; k < 8; k++) {
        float sn = sk * c1 + ck * s1;
        float cn = ck * c1 - sk * s1;
        sk = sn; ck = cn;
        ef[k] = pref * sk;
    }
    float4* dst = (float4*)(d_ef + (size_t)e * 8);
    dst[0] = make_float4(ef[0], ef[1], ef[2], ef[3]);
    dst[1] = make_float4(ef[4], ef[5], ef[6], ef[7]);
}

// ---------------------------------------------------------------------------
// Weight prep (17 blocks)
// ---------------------------------------------------------------------------
__global__ void __launch_bounds__(256) k_prepw(
    const float* __restrict__ embW, const float* __restrict__ LU0_l0,
    const float* __restrict__ PL0_l0, const float* __restrict__ LU0_l1,
    const float* __restrict__ PL1_l0, const float* __restrict__ LU1_l1)
{
    int tid = threadIdx.x;
    int b = blockIdx.x;
    if (b == 16) {
        int s = tid >> 6, j = tid & 63;
        float acc = 0.0f;
        for (int k = 0; k < 64; k++) acc += embW[s * 64 + k] * LU0_l0[k * 64 + j];
        d_U[tid] = acc;
        return;
    }
    int t = b * 256 + tid;
    int i = t >> 6, j = t & 63;
    float a0 = 0.0f, a1 = 0.0f;
    for (int k = 0; k < 64; k++) {
        a0 += PL0_l0[i * 64 + k] * LU0_l1[k * 64 + j];
        a1 += PL1_l0[i * 64 + k] * LU1_l1[k * 64 + j];
    }
    d_W0c[t] = a0;
    d_W1c[t] = a1;
}

// ---------------------------------------------------------------------------
// Layer-0 seed
// ---------------------------------------------------------------------------
__global__ void k_seed(const int* __restrict__ species, int N_) {
    int idx = blockIdx.x * blockDim.x + threadIdx.x;
    if (idx >= N_ * CCH) return;
    int n = idx >> 6, c = idx & 63;
    int sp = species[n];
    d_x[idx] = make_float4(d_U[sp * CCH + c], 0.0f, 0.0f, 0.0f);
    d_M[idx] = make_float4(0, 0, 0, 0);
}

// ---------------------------------------------------------------------------
// Persistent fused edge kernel: two independent 8-warp groups (named
// barriers), shared weights. No staging of EF/Y/idx: B reads EF via
// broadcast LDG; D's epilogue holds edge metadata in shuffled registers
// and batch-prefetches xs gathers (MLP 4/2) to collapse the latency chain.
// ---------------------------------------------------------------------------
#define SME_W1   0
#define SME_W2   512
#define SME_W3   4608
#define SME_GRP  25088
#define GRP_FL   8704    /* floats per group block: gHa + gHb */
#define SME_TOT  (SME_GRP + 2 * GRP_FL)   /* 42496 floats = 166 KB */
#define GO_HA    0
#define GO_HB    4352

template<bool FIRST>
__device__ __forceinline__ void emit_msg(float* dst, float4 xs, float4 Yv,
                                         float t0, float t1, float t2,
                                         float t3, float t4) {
    const float INV_SQRT3 = 0.5773502691896258f;
    const float INV_SQRT2 = 0.7071067811865475f;
    float m0, m1x, m1y, m1z;
    if (FIRST) {
        m0 = t0 * xs.x;
        float a = t1 * xs.x;
        m1x = a * Yv.x;
        m1y = a * Yv.y;
        m1z = a * Yv.z;
    } else {
        float dotv = xs.y * Yv.x + xs.z * Yv.y + xs.w * Yv.z;
        m0 = t0 * xs.x + t3 * dotv * INV_SQRT3;
        float cx = xs.z * Yv.z - xs.w * Yv.y;
        float cy = xs.w * Yv.x - xs.y * Yv.z;
        float cz = xs.y * Yv.y - xs.z * Yv.x;
        float a = t1 * xs.x;
        float t4s = t4 * INV_SQRT2;
        m1x = a * Yv.x + t2 * xs.y + t4s * cx;
        m1y = a * Yv.y + t2 * xs.z + t4s * cy;
        m1z = a * Yv.z + t2 * xs.w + t4s * cz;
    }
    asm volatile("red.global.add.v4.f32 [%0], {%1,%2,%3,%4};"
                 :: "l"(dst), "f"(m0), "f"(m1x), "f"(m1y), "f"(m1z)
                 : "memory");
}

template<bool FIRST>
__global__ void __launch_bounds__(ETHREADS, 1) k_edge(
    const int* __restrict__ ei,
    const float* __restrict__ W1g, const float* __restrict__ W2g,
    const float* __restrict__ W3g, int E_)
{
    extern __shared__ float sm[];
    float* sW1 = sm + SME_W1;
    float* sW2 = sm + SME_W2;
    float* sW3 = sm + SME_W3;
    const int tid = threadIdx.x;
    const int gid = tid >> 8;          // group 0 or 1
    const int ltid = tid & 255;        // thread within group
    const int lane = tid & 31;
    const int wl = ltid >> 5;          // warp within group, 0..7
    constexpr int NB = FIRST ? 2 : 5;
    constexpr int EB = FIRST ? 4 : 2;  // emission prefetch batch

    float* GB = sm + SME_GRP + gid * GRP_FL;
    float* gHa = GB + GO_HA;           // [64][68]
    float* gHb = GB + GO_HB;           // [64][68]

    // shared one-time weight load
    for (int i = tid; i < 512; i += ETHREADS) sW1[i] = W1g[i];
    for (int i = tid; i < 4096; i += ETHREADS) sW2[i] = W2g[i];
    for (int i = tid; i < 20480; i += ETHREADS) sW3[i] = W3g[i];
    __syncthreads();

    const int barid = gid + 1;
    #define BARG() asm volatile("bar.sync %0, 256;" :: "r"(barid) : "memory")

    int nTiles = (E_ + GTILE - 1) / GTILE;
    for (long long t = (long long)blockIdx.x * 2 + gid; t < nTiles;
         t += (long long)EGRID * 2) {
        long long base = t * GTILE;

        // Phase B: H1 = silu(EF @ W1). EF read directly (warp-uniform LDG).
        #pragma unroll
        for (int i = 0; i < 16; i++) {
            int idx = ltid + 256 * i;
            int e = idx >> 6, j = idx & 63;
            long long ge = base + e;
            float4 efa = make_float4(0, 0, 0, 0), efb = efa;
            if (ge < E_) {
                const float4* efp = (const float4*)(d_ef + (size_t)ge * 8);
                efa = efp[0];
                efb = efp[1];
            }
            float acc = efa.x * sW1[j] + efa.y * sW1[64 + j]
                      + efa.z * sW1[128 + j] + efa.w * sW1[192 + j]
                      + efb.x * sW1[256 + j] + efb.y * sW1[320 + j]
                      + efb.z * sW1[384 + j] + efb.w * sW1[448 + j];
            gHa[e * HSTR + j] = silu_f(acc);
        }
        BARG();

        // Phase C: H2 = silu(H1 @ W2), 4 edges x 4 cols, float2 K-batch
        {
            int e0 = (ltid >> 4) << 2;
            int j0 = (ltid & 15) << 2;
            unsigned long long acc[4][2] = {};
            #pragma unroll 2
            for (int cc = 0; cc < 64; cc += 2) {
                float2 a[4];
                #pragma unroll
                for (int i = 0; i < 4; i++)
                    a[i] = *(const float2*)&gHa[(e0 + i) * HSTR + cc];
                #pragma unroll
                for (int k = 0; k < 2; k++) {
                    const unsigned long long* bp =
                        (const unsigned long long*)&sW2[(cc + k) * 64 + j0];
                    unsigned long long b0 = bp[0], b1 = bp[1];
                    #pragma unroll
                    for (int i = 0; i < 4; i++) {
                        unsigned long long a2 = pack2(k ? a[i].y : a[i].x);
                        fma2(acc[i][0], a2, b0);
                        fma2(acc[i][1], a2, b1);
                    }
                }
            }
            #pragma unroll
            for (int i = 0; i < 4; i++) {
                float2 p0 = unpack2(acc[i][0]);
                float2 p1 = unpack2(acc[i][1]);
                float* dst = &gHb[(e0 + i) * HSTR + j0];
                dst[0] = silu_f(p0.x);
                dst[1] = silu_f(p0.y);
                dst[2] = silu_f(p1.x);
                dst[3] = silu_f(p1.y);
            }
        }
        BARG();

        // Phase D+E fused: warp owns 8 edges; thread owns a channel pair.
        // Edge metadata loaded up-front into lane registers (shuffle later).
        {
            int eb = wl * 8;
            int cb = lane * 2;
            // metadata for edge eb + (lane&7)
            long long ge = base + eb + (lane & 7);
            int sv = 0, rv = -1;
            float yx = 0, yy = 0, yz = 0;
            if (ge < E_) {
                sv = ei[ge];
                rv = ei[E_ + ge];
                float4 y = d_Y[ge];
                yx = y.x; yy = y.y; yz = y.z;
            }

            unsigned long long acc[8][NB];
            #pragma unroll
            for (int ii = 0; ii < 8; ii++)
                #pragma unroll
                for (int p = 0; p < NB; p++) acc[ii][p] = 0ull;

            #pragma unroll 1
            for (int cc = 0; cc < 64; cc += 2) {
                float2 a[8];
                #pragma unroll
                for (int ii = 0; ii < 8; ii++)
                    a[ii] = *(const float2*)&gHb[(eb + ii) * HSTR + cc];
                #pragma unroll
                for (int k = 0; k < 2; k++) {
                    const float* wrow = &sW3[(cc + k) * 320 + cb];
                    unsigned long long b[NB];
                    #pragma unroll
                    for (int p = 0; p < NB; p++)
                        b[p] = *(const unsigned long long*)(wrow + 64 * p);
                    #pragma unroll
                    for (int ii = 0; ii < 8; ii++) {
                        unsigned long long a2 = pack2(k ? a[ii].y : a[ii].x);
                        #pragma unroll
                        for (int p = 0; p < NB; p++) fma2(acc[ii][p], a2, b[p]);
                    }
                }
            }

            // emission in prefetch batches of EB edges (MLP on xs gathers)
            #pragma unroll
            for (int bb = 0; bb < 8 / EB; bb++) {
                int rr[EB];
                float4 Yv[EB], xs0[EB], xs1[EB];
                float* dstp[EB];
                #pragma unroll
                for (int j = 0; j < EB; j++) {
                    int ii = bb * EB + j;
                    int s = __shfl_sync(0xffffffffu, sv, ii);
                    rr[j] = __shfl_sync(0xffffffffu, rv, ii);
                    Yv[j].x = __shfl_sync(0xffffffffu, yx, ii);
                    Yv[j].y = __shfl_sync(0xffffffffu, yy, ii);
                    Yv[j].z = __shfl_sync(0xffffffffu, yz, ii);
                    Yv[j].w = 0.0f;
                    const float4* xp = &d_x[(size_t)s * CCH + cb];
                    xs0[j] = xp[0];
                    xs1[j] = xp[1];
                    dstp[j] = (float*)&d_M[(size_t)rr[j] * CCH + cb];
                }
                #pragma unroll
                for (int j = 0; j < EB; j++) {
                    if (rr[j] < 0) continue;
                    int ii = bb * EB + j;
                    float2 t0 = unpack2(acc[ii][0]);
                    float2 t1 = unpack2(acc[ii][1]);
                    float2 t2 = make_float2(0, 0), t3 = make_float2(0, 0), t4 = make_float2(0, 0);
                    if (!FIRST) {
                        t2 = unpack2(acc[ii][2]);
                        t3 = unpack2(acc[ii][3]);
                        t4 = unpack2(acc[ii][4]);
                    }
                    emit_msg<FIRST>(dstp[j],     xs0[j], Yv[j], t0.x, t1.x, t2.x, t3.x, t4.x);
                    emit_msg<FIRST>(dstp[j] + 4, xs1[j], Yv[j], t0.y, t1.y, t2.y, t3.y, t4.y);
                }
            }
        }
        BARG();
    }
    #undef BARG
}

// ---------------------------------------------------------------------------
// Fused post(l0)+up(l1) / final post
// ---------------------------------------------------------------------------
#define SMP_LW0 0
#define SMP_LW1 4096
#define SMP_PL0 8192
#define SMP_PL1 12288
#define SMP_PW0 16384
#define SMP_PW1 17152
#define SMP_A   17664
#define SMP_B   18688
#define SMP_TOT 19712   // floats

template<bool FINAL>
__global__ void __launch_bounds__(256) k_post(
    const int* __restrict__ species,
    const float* __restrict__ LW0g, const float* __restrict__ LW1g,
    const float* __restrict__ PW0g, const float* __restrict__ PW1g,
    const float* __restrict__ PL0g, const float* __restrict__ PL1g,
    float4* __restrict__ out, int N_)
{
    extern __shared__ float sm[];
    float* sLW0 = sm + SMP_LW0;
    float* sLW1 = sm + SMP_LW1;
    float* sPL0 = sm + SMP_PL0;
    float* sPL1 = sm + SMP_PL1;
    float* sPW0 = sm + SMP_PW0;
    float* sPW1 = sm + SMP_PW1;
    float4* sA = (float4*)(sm + SMP_A);
    float4* sB = (float4*)(sm + SMP_B);
    int tid = threadIdx.x;
    const float INV_SQRT3 = 0.5773502691896258f;
    for (int i = tid; i < 4096; i += 256) {
        sLW0[i] = LW0g[i];
        sLW1[i] = LW1g[i];
        sPL0[i] = PL0g[i];
        sPL1[i] = PL1g[i];
    }
    for (int i = tid; i < 768; i += 256) sPW0[i] = PW0g[i];
    for (int i = tid; i < 512; i += 256) sPW1[i] = PW1g[i];
    __syncthreads();

    int base = blockIdx.x * 64;
    int c = tid & 63, sub = tid >> 6;
    for (int g = 0; g < 16; g++) {
        int n = base + g * 4 + sub;
        bool act = n < N_;
        if (act) {
            float4 mv = d_M[(size_t)n * CCH + c];
            mv.x *= 0.0625f; mv.y *= 0.0625f; mv.z *= 0.0625f; mv.w *= 0.0625f;
            sA[sub * CCH + c] = mv;
        }
        __syncthreads();
        if (act) {
            float h0 = 0, h1x = 0, h1y = 0, h1z = 0;
            const float4* ar = &sA[sub * CCH];
            #pragma unroll 8
            for (int cc = 0; cc < 64; cc++) {
                float4 a = ar[cc];
                float w0 = sLW0[cc * 64 + c];
                float w1 = sLW1[cc * 64 + c];
                h0 += a.x * w0;
                h1x += a.y * w1;
                h1y += a.z * w1;
                h1z += a.w * w1;
            }
            int sp = species[n];
            float nrm = (h1x * h1x + h1y * h1y + h1z * h1z) * INV_SQRT3;
            const float* p0 = &sPW0[sp * 192 + c];
            float b0 = p0[0] * h0 + p0[64] * h0 * h0 + p0[128] * nrm;
            const float* p1 = &sPW1[sp * 128 + c];
            float q = p1[0] + p1[64] * h0;
            sB[sub * CCH + c] = make_float4(b0, q * h1x, q * h1y, q * h1z);
        }
        __syncthreads();
        if (act) {
            float o0 = 0, o1 = 0, o2 = 0, o3 = 0;
            const float4* br = &sB[sub * CCH];
            #pragma unroll 8
            for (int cc = 0; cc < 64; cc++) {
                float4 b = br[cc];
                float w0 = sPL0[cc * 64 + c];
                float w1 = sPL1[cc * 64 + c];
                o0 += b.x * w0;
                o1 += b.y * w1;
                o2 += b.z * w1;
                o3 += b.w * w1;
            }
            if (FINAL) {
                out[(size_t)n * CCH + c] = make_float4(o0, o1, o2, o3);
            } else {
                d_x[(size_t)n * CCH + c] = make_float4(o0, o1, o2, o3);
                d_M[(size_t)n * CCH + c] = make_float4(0, 0, 0, 0);
            }
        }
        __syncthreads();
    }
}

// ---------------------------------------------------------------------------
extern "C" void kernel_launch(void* const* d_in, const int* in_sizes, int n_in,
                              void* d_out, int out_size) {
    const float* positions    = (const float*)d_in[0];
    const int*   species      = (const int*)d_in[1];
    const int*   edge_index   = (const int*)d_in[2];
    const float* node_embed_W = (const float*)d_in[3];
    const float* lin_up_W0    = (const float*)d_in[4];
    const float* lin_up_W1    = (const float*)d_in[5];
    const float* mlp_W1       = (const float*)d_in[6];
    const float* mlp_W2       = (const float*)d_in[7];
    const float* mlp_W3       = (const float*)d_in[8];
    const float* lin_W0       = (const float*)d_in[9];
    const float* lin_W1       = (const float*)d_in[10];
    const float* prod_W0      = (const float*)d_in[11];
    const float* prod_W1      = (const float*)d_in[12];
    const float* prod_lin_W0  = (const float*)d_in[13];
    const float* prod_lin_W1  = (const float*)d_in[14];

    int N_ = in_sizes[0] / 3;
    int E_ = in_sizes[2] / 2;

    size_t smemE = (size_t)SME_TOT * 4;
    size_t smemP = (size_t)SMP_TOT * 4;
    cudaFuncSetAttribute(k_edge<true>,  cudaFuncAttributeMaxDynamicSharedMemorySize, (int)smemE);
    cudaFuncSetAttribute(k_edge<false>, cudaFuncAttributeMaxDynamicSharedMemorySize, (int)smemE);
    cudaFuncSetAttribute(k_post<true>,  cudaFuncAttributeMaxDynamicSharedMemorySize, (int)smemP);
    cudaFuncSetAttribute(k_post<false>, cudaFuncAttributeMaxDynamicSharedMemorySize, (int)smemP);

    k_geom<<<(E_ + 255) / 256, 256>>>(positions, edge_index, E_);
    k_prepw<<<17, 256>>>(node_embed_W, lin_up_W0,
                         prod_lin_W0, lin_up_W0 + 4096,
                         prod_lin_W1, lin_up_W1 + 4096);
    k_seed<<<(N_ * CCH + 255) / 256, 256>>>(species, N_);

    void* p0;
    void* p1;
    cudaGetSymbolAddress(&p0, d_W0c);
    cudaGetSymbolAddress(&p1, d_W1c);
    const float* W0c_sym = (const float*)p0;
    const float* W1c_sym = (const float*)p1;

    // layer 0
    k_edge<true><<<EGRID, ETHREADS, smemE>>>(edge_index, mlp_W1, mlp_W2, mlp_W3, E_);
    k_post<false><<<(N_ + 63) / 64, 256, smemP>>>(
        species, lin_W0, lin_W1, prod_W0, prod_W1,
        W0c_sym, W1c_sym, nullptr, N_);

    // layer 1
    k_edge<false><<<EGRID, ETHREADS, smemE>>>(
        edge_index, mlp_W1 + 512, mlp_W2 + 4096, mlp_W3 + 20480, E_);
    k_post<true><<<(N_ + 63) / 64, 256, smemP>>>(
        species, lin_W0 + 4096, lin_W1 + 4096,
        prod_W0 + 768, prod_W1 + 512,
        prod_lin_W0 + 4096, prod_lin_W1 + 4096,
        (float4*)d_out, N_);
}

// round 16
// speedup vs baseline: 1.6711x; 1.1507x over previous
#include <cuda_runtime.h>
#include <cstdint>

#define N_MAX 25000
#define E_MAX 400000
#define CCH 64
#define ETHREADS 512
#define EGRID 148
#define GTILE 64
#define HSTR 68

static __device__ float4 d_x[N_MAX * CCH];   // up-projected  [N][C][4]
static __device__ float4 d_M[N_MAX * CCH];   // scatter accum [N][C][4]
static __device__ float  d_ef[E_MAX * 8];    // edge bessel feats
static __device__ float4 d_Y[E_MAX];         // sqrt3 * unit vec (w unused)
static __device__ float  d_U[4 * CCH];       // embW @ lin_up_W0[0]
static __device__ float  d_W0c[CCH * CCH];   // prod_lin_W0[0] @ lin_up_W0[1]
static __device__ float  d_W1c[CCH * CCH];   // prod_lin_W1[0] @ lin_up_W1[1]

__device__ __forceinline__ float silu_f(float v) {
    return v / (1.0f + __expf(-v));
}
__device__ __forceinline__ unsigned long long pack2(float x) {
    unsigned long long r;
    asm("mov.b64 %0, {%1, %1};" : "=l"(r) : "f"(x));
    return r;
}
__device__ __forceinline__ void fma2(unsigned long long &d, unsigned long long a, unsigned long long b) {
    asm("fma.rn.f32x2 %0, %1, %2, %0;" : "+l"(d) : "l"(a), "l"(b));
}
__device__ __forceinline__ float2 unpack2(unsigned long long v) {
    float2 r;
    asm("mov.b64 {%0, %1}, %2;" : "=f"(r.x), "=f"(r.y) : "l"(v));
    return r;
}

// ---------------------------------------------------------------------------
// Per-edge geometry: one sincosf + exact angle-addition recurrence
// ---------------------------------------------------------------------------
__global__ void k_geom(const float* __restrict__ pos, const int* __restrict__ ei, int E_) {
    int e = blockIdx.x * blockDim.x + threadIdx.x;
    if (e >= E_) return;
    int s = ei[e];
    int r_ = ei[E_ + e];
    float vx = pos[3*s + 0] - pos[3*r_ + 0];
    float vy = pos[3*s + 1] - pos[3*r_ + 1];
    float vz = pos[3*s + 2] - pos[3*r_ + 2];
    float rr = sqrtf(vx*vx + vy*vy + vz*vz);
    rr = fmaxf(rr, 1e-6f);
    float inv_r = 1.0f / rr;
    const float SQRT3 = 1.7320508075688772f;
    float4 Y;
    Y.x = SQRT3 * vx * inv_r;
    Y.y = SQRT3 * vy * inv_r;
    Y.z = SQRT3 * vz * inv_r;
    Y.w = 0.0f;
    d_Y[e] = Y;
    float x = rr * 0.2f;
    float x2 = x * x;
    float x6 = x2 * x2 * x2;
    float fc = 1.0f - 28.0f*x6 + 48.0f*x6*x - 21.0f*x6*x2;
    fc = (x < 1.0f) ? fc : 0.0f;
    const float BC = 0.6324555320336759f;      // sqrt(2/5)
    const float PI_O_R = 0.6283185307179586f;  // pi/5
    float pref = BC * inv_r * fc;
    float theta = PI_O_R * rr;
    float s1, c1;
    sincosf(theta, &s1, &c1);
    float ef[8];
    float sk = s1, ck = c1;
    ef[0] = pref * sk;
    #pragma unroll
    for (int k = 1; k < 8; k++) {
        float sn = sk * c1 + ck * s1;
        float cn = ck * c1 - sk * s1;
        sk = sn; ck = cn;
        ef[k] = pref * sk;
    }
    float4* dst = (float4*)(d_ef + (size_t)e * 8);
    dst[0] = make_float4(ef[0], ef[1], ef[2], ef[3]);
    dst[1] = make_float4(ef[4], ef[5], ef[6], ef[7]);
}

// ---------------------------------------------------------------------------
// Weight prep (17 blocks)
// ---------------------------------------------------------------------------
__global__ void __launch_bounds__(256) k_prepw(
    const float* __restrict__ embW, const float* __restrict__ LU0_l0,
    const float* __restrict__ PL0_l0, const float* __restrict__ LU0_l1,
    const float* __restrict__ PL1_l0, const float* __restrict__ LU1_l1)
{
    int tid = threadIdx.x;
    int b = blockIdx.x;
    if (b == 16) {
        int s = tid >> 6, j = tid & 63;
        float acc = 0.0f;
        for (int k = 0; k < 64; k++) acc += embW[s * 64 + k] * LU0_l0[k * 64 + j];
        d_U[tid] = acc;
        return;
    }
    int t = b * 256 + tid;
    int i = t >> 6, j = t & 63;
    float a0 = 0.0f, a1 = 0.0f;
    for (int k = 0; k < 64; k++) {
        a0 += PL0_l0[i * 64 + k] * LU0_l1[k * 64 + j];
        a1 += PL1_l0[i * 64 + k] * LU1_l1[k * 64 + j];
    }
    d_W0c[t] = a0;
    d_W1c[t] = a1;
}

// ---------------------------------------------------------------------------
// Layer-0 seed
// ---------------------------------------------------------------------------
__global__ void k_seed(const int* __restrict__ species, int N_) {
    int idx = blockIdx.x * blockDim.x + threadIdx.x;
    if (idx >= N_ * CCH) return;
    int n = idx >> 6, c = idx & 63;
    int sp = species[n];
    d_x[idx] = make_float4(d_U[sp * CCH + c], 0.0f, 0.0f, 0.0f);
    d_M[idx] = make_float4(0, 0, 0, 0);
}

// ---------------------------------------------------------------------------
// Persistent fused edge kernel: two independent 8-warp groups (named
// barriers), shared weights. EF cooperatively staged to SMEM (r14);
// D+E epilogue keeps edge metadata in shuffled registers and batch-
// prefetches xs gathers (r15).
// ---------------------------------------------------------------------------
#define SME_W1   0
#define SME_W2   512
#define SME_W3   4608
#define SME_GRP  25088
#define GRP_FL   9216    /* floats per group: gEF(512) + gHa(4352) + gHb(4352) */
#define SME_TOT  (SME_GRP + 2 * GRP_FL)   /* 43520 floats = 170 KB */
#define GO_EF    0
#define GO_HA    512
#define GO_HB    4864

template<bool FIRST>
__device__ __forceinline__ void emit_msg(float* dst, float4 xs, float4 Yv,
                                         float t0, float t1, float t2,
                                         float t3, float t4) {
    const float INV_SQRT3 = 0.5773502691896258f;
    const float INV_SQRT2 = 0.7071067811865475f;
    float m0, m1x, m1y, m1z;
    if (FIRST) {
        m0 = t0 * xs.x;
        float a = t1 * xs.x;
        m1x = a * Yv.x;
        m1y = a * Yv.y;
        m1z = a * Yv.z;
    } else {
        float dotv = xs.y * Yv.x + xs.z * Yv.y + xs.w * Yv.z;
        m0 = t0 * xs.x + t3 * dotv * INV_SQRT3;
        float cx = xs.z * Yv.z - xs.w * Yv.y;
        float cy = xs.w * Yv.x - xs.y * Yv.z;
        float cz = xs.y * Yv.y - xs.z * Yv.x;
        float a = t1 * xs.x;
        float t4s = t4 * INV_SQRT2;
        m1x = a * Yv.x + t2 * xs.y + t4s * cx;
        m1y = a * Yv.y + t2 * xs.z + t4s * cy;
        m1z = a * Yv.z + t2 * xs.w + t4s * cz;
    }
    asm volatile("red.global.add.v4.f32 [%0], {%1,%2,%3,%4};"
                 :: "l"(dst), "f"(m0), "f"(m1x), "f"(m1y), "f"(m1z)
                 : "memory");
}

template<bool FIRST>
__global__ void __launch_bounds__(ETHREADS, 1) k_edge(
    const int* __restrict__ ei,
    const float* __restrict__ W1g, const float* __restrict__ W2g,
    const float* __restrict__ W3g, int E_)
{
    extern __shared__ float sm[];
    float* sW1 = sm + SME_W1;
    float* sW2 = sm + SME_W2;
    float* sW3 = sm + SME_W3;
    const int tid = threadIdx.x;
    const int gid = tid >> 8;          // group 0 or 1
    const int ltid = tid & 255;        // thread within group
    const int lane = tid & 31;
    const int wl = ltid >> 5;          // warp within group, 0..7
    constexpr int NB = FIRST ? 2 : 5;
    constexpr int EB = FIRST ? 4 : 2;  // emission prefetch batch

    float* GB = sm + SME_GRP + gid * GRP_FL;
    float* gEF = GB + GO_EF;           // [64][8]
    float* gHa = GB + GO_HA;           // [64][68]
    float* gHb = GB + GO_HB;           // [64][68]

    // shared one-time weight load
    for (int i = tid; i < 512; i += ETHREADS) sW1[i] = W1g[i];
    for (int i = tid; i < 4096; i += ETHREADS) sW2[i] = W2g[i];
    for (int i = tid; i < 20480; i += ETHREADS) sW3[i] = W3g[i];
    __syncthreads();

    const int barid = gid + 1;
    #define BARG() asm volatile("bar.sync %0, 256;" :: "r"(barid) : "memory")

    int nTiles = (E_ + GTILE - 1) / GTILE;
    for (long long t = (long long)blockIdx.x * 2 + gid; t < nTiles;
         t += (long long)EGRID * 2) {
        long long base = t * GTILE;

        BARG();   // prev tile fully consumed by this group
        // cooperative EF staging: 128 threads x 16B
        if (ltid < 128) {
            long long e = base + (ltid >> 1);
            float4 v = make_float4(0, 0, 0, 0);
            if (e < E_) v = ((const float4*)d_ef)[e * 2 + (ltid & 1)];
            ((float4*)gEF)[ltid] = v;
        }
        BARG();

        // Phase B: H1 = silu(EF @ W1)  [64x8]@[8x64], 16 outputs/thread
        #pragma unroll
        for (int i = 0; i < 16; i++) {
            int idx = ltid + 256 * i;
            int e = idx >> 6, j = idx & 63;
            float acc = 0.0f;
            #pragma unroll
            for (int k = 0; k < 8; k++) acc += gEF[e * 8 + k] * sW1[k * 64 + j];
            gHa[e * HSTR + j] = silu_f(acc);
        }
        BARG();

        // Phase C: H2 = silu(H1 @ W2), 4 edges x 4 cols, float2 K-batch
        {
            int e0 = (ltid >> 4) << 2;
            int j0 = (ltid & 15) << 2;
            unsigned long long acc[4][2] = {};
            #pragma unroll 2
            for (int cc = 0; cc < 64; cc += 2) {
                float2 a[4];
                #pragma unroll
                for (int i = 0; i < 4; i++)
                    a[i] = *(const float2*)&gHa[(e0 + i) * HSTR + cc];
                #pragma unroll
                for (int k = 0; k < 2; k++) {
                    const unsigned long long* bp =
                        (const unsigned long long*)&sW2[(cc + k) * 64 + j0];
                    unsigned long long b0 = bp[0], b1 = bp[1];
                    #pragma unroll
                    for (int i = 0; i < 4; i++) {
                        unsigned long long a2 = pack2(k ? a[i].y : a[i].x);
                        fma2(acc[i][0], a2, b0);
                        fma2(acc[i][1], a2, b1);
                    }
                }
            }
            #pragma unroll
            for (int i = 0; i < 4; i++) {
                float2 p0 = unpack2(acc[i][0]);
                float2 p1 = unpack2(acc[i][1]);
                float* dst = &gHb[(e0 + i) * HSTR + j0];
                dst[0] = silu_f(p0.x);
                dst[1] = silu_f(p0.y);
                dst[2] = silu_f(p1.x);
                dst[3] = silu_f(p1.y);
            }
        }
        BARG();

        // Phase D+E fused: warp owns 8 edges; thread owns a channel pair.
        // Edge metadata in lane registers (shuffled in the epilogue).
        {
            int eb = wl * 8;
            int cb = lane * 2;
            long long ge = base + eb + (lane & 7);
            int sv = 0, rv = -1;
            float yx = 0, yy = 0, yz = 0;
            if (ge < E_) {
                sv = ei[ge];
                rv = ei[E_ + ge];
                float4 y = d_Y[ge];
                yx = y.x; yy = y.y; yz = y.z;
            }

            unsigned long long acc[8][NB];
            #pragma unroll
            for (int ii = 0; ii < 8; ii++)
                #pragma unroll
                for (int p = 0; p < NB; p++) acc[ii][p] = 0ull;

            #pragma unroll 1
            for (int cc = 0; cc < 64; cc += 2) {
                float2 a[8];
                #pragma unroll
                for (int ii = 0; ii < 8; ii++)
                    a[ii] = *(const float2*)&gHb[(eb + ii) * HSTR + cc];
                #pragma unroll
                for (int k = 0; k < 2; k++) {
                    const float* wrow = &sW3[(cc + k) * 320 + cb];
                    unsigned long long b[NB];
                    #pragma unroll
                    for (int p = 0; p < NB; p++)
                        b[p] = *(const unsigned long long*)(wrow + 64 * p);
                    #pragma unroll
                    for (int ii = 0; ii < 8; ii++) {
                        unsigned long long a2 = pack2(k ? a[ii].y : a[ii].x);
                        #pragma unroll
                        for (int p = 0; p < NB; p++) fma2(acc[ii][p], a2, b[p]);
                    }
                }
            }

            // emission in prefetch batches of EB edges (MLP on xs gathers)
            #pragma unroll
            for (int bb = 0; bb < 8 / EB; bb++) {
                int rr[EB];
                float4 Yv[EB], xs0[EB], xs1[EB];
                float* dstp[EB];
                #pragma unroll
                for (int j = 0; j < EB; j++) {
                    int ii = bb * EB + j;
                    int s = __shfl_sync(0xffffffffu, sv, ii);
                    rr[j] = __shfl_sync(0xffffffffu, rv, ii);
                    Yv[j].x = __shfl_sync(0xffffffffu, yx, ii);
                    Yv[j].y = __shfl_sync(0xffffffffu, yy, ii);
                    Yv[j].z = __shfl_sync(0xffffffffu, yz, ii);
                    Yv[j].w = 0.0f;
                    const float4* xp = &d_x[(size_t)s * CCH + cb];
                    xs0[j] = xp[0];
                    xs1[j] = xp[1];
                    dstp[j] = (float*)&d_M[(size_t)rr[j] * CCH + cb];
                }
                #pragma unroll
                for (int j = 0; j < EB; j++) {
                    if (rr[j] < 0) continue;
                    int ii = bb * EB + j;
                    float2 t0 = unpack2(acc[ii][0]);
                    float2 t1 = unpack2(acc[ii][1]);
                    float2 t2 = make_float2(0, 0), t3 = make_float2(0, 0), t4 = make_float2(0, 0);
                    if (!FIRST) {
                        t2 = unpack2(acc[ii][2]);
                        t3 = unpack2(acc[ii][3]);
                        t4 = unpack2(acc[ii][4]);
                    }
                    emit_msg<FIRST>(dstp[j],     xs0[j], Yv[j], t0.x, t1.x, t2.x, t3.x, t4.x);
                    emit_msg<FIRST>(dstp[j] + 4, xs1[j], Yv[j], t0.y, t1.y, t2.y, t3.y, t4.y);
                }
            }
        }
    }
    #undef BARG
}

// ---------------------------------------------------------------------------
// Fused post(l0)+up(l1) / final post
// ---------------------------------------------------------------------------
#define SMP_LW0 0
#define SMP_LW1 4096
#define SMP_PL0 8192
#define SMP_PL1 12288
#define SMP_PW0 16384
#define SMP_PW1 17152
#define SMP_A   17664
#define SMP_B   18688
#define SMP_TOT 19712   // floats

template<bool FINAL>
__global__ void __launch_bounds__(256) k_post(
    const int* __restrict__ species,
    const float* __restrict__ LW0g, const float* __restrict__ LW1g,
    const float* __restrict__ PW0g, const float* __restrict__ PW1g,
    const float* __restrict__ PL0g, const float* __restrict__ PL1g,
    float4* __restrict__ out, int N_)
{
    extern __shared__ float sm[];
    float* sLW0 = sm + SMP_LW0;
    float* sLW1 = sm + SMP_LW1;
    float* sPL0 = sm + SMP_PL0;
    float* sPL1 = sm + SMP_PL1;
    float* sPW0 = sm + SMP_PW0;
    float* sPW1 = sm + SMP_PW1;
    float4* sA = (float4*)(sm + SMP_A);
    float4* sB = (float4*)(sm + SMP_B);
    int tid = threadIdx.x;
    const float INV_SQRT3 = 0.5773502691896258f;
    for (int i = tid; i < 4096; i += 256) {
        sLW0[i] = LW0g[i];
        sLW1[i] = LW1g[i];
        sPL0[i] = PL0g[i];
        sPL1[i] = PL1g[i];
    }
    for (int i = tid; i < 768; i += 256) sPW0[i] = PW0g[i];
    for (int i = tid; i < 512; i += 256) sPW1[i] = PW1g[i];
    __syncthreads();

    int base = blockIdx.x * 64;
    int c = tid & 63, sub = tid >> 6;
    for (int g = 0; g < 16; g++) {
        int n = base + g * 4 + sub;
        bool act = n < N_;
        if (act) {
            float4 mv = d_M[(size_t)n * CCH + c];
            mv.x *= 0.0625f; mv.y *= 0.0625f; mv.z *= 0.0625f; mv.w *= 0.0625f;
            sA[sub * CCH + c] = mv;
        }
        __syncthreads();
        if (act) {
            float h0 = 0, h1x = 0, h1y = 0, h1z = 0;
            const float4* ar = &sA[sub * CCH];
            #pragma unroll 8
            for (int cc = 0; cc < 64; cc++) {
                float4 a = ar[cc];
                float w0 = sLW0[cc * 64 + c];
                float w1 = sLW1[cc * 64 + c];
                h0 += a.x * w0;
                h1x += a.y * w1;
                h1y += a.z * w1;
                h1z += a.w * w1;
            }
            int sp = species[n];
            float nrm = (h1x * h1x + h1y * h1y + h1z * h1z) * INV_SQRT3;
            const float* p0 = &sPW0[sp * 192 + c];
            float b0 = p0[0] * h0 + p0[64] * h0 * h0 + p0[128] * nrm;
            const float* p1 = &sPW1[sp * 128 + c];
            float q = p1[0] + p1[64] * h0;
            sB[sub * CCH + c] = make_float4(b0, q * h1x, q * h1y, q * h1z);
        }
        __syncthreads();
        if (act) {
            float o0 = 0, o1 = 0, o2 = 0, o3 = 0;
            const float4* br = &sB[sub * CCH];
            #pragma unroll 8
            for (int cc = 0; cc < 64; cc++) {
                float4 b = br[cc];
                float w0 = sPL0[cc * 64 + c];
                float w1 = sPL1[cc * 64 + c];
                o0 += b.x * w0;
                o1 += b.y * w1;
                o2 += b.z * w1;
                o3 += b.w * w1;
            }
            if (FINAL) {
                out[(size_t)n * CCH + c] = make_float4(o0, o1, o2, o3);
            } else {
                d_x[(size_t)n * CCH + c] = make_float4(o0, o1, o2, o3);
                d_M[(size_t)n * CCH + c] = make_float4(0, 0, 0, 0);
            }
        }
        __syncthreads();
    }
}

// ---------------------------------------------------------------------------
extern "C" void kernel_launch(void* const* d_in, const int* in_sizes, int n_in,
                              void* d_out, int out_size) {
    const float* positions    = (const float*)d_in[0];
    const int*   species      = (const int*)d_in[1];
    const int*   edge_index   = (const int*)d_in[2];
    const float* node_embed_W = (const float*)d_in[3];
    const float* lin_up_W0    = (const float*)d_in[4];
    const float* lin_up_W1    = (const float*)d_in[5];
    const float* mlp_W1       = (const float*)d_in[6];
    const float* mlp_W2       = (const float*)d_in[7];
    const float* mlp_W3       = (const float*)d_in[8];
    const float* lin_W0       = (const float*)d_in[9];
    const float* lin_W1       = (const float*)d_in[10];
    const float* prod_W0      = (const float*)d_in[11];
    const float* prod_W1      = (const float*)d_in[12];
    const float* prod_lin_W0  = (const float*)d_in[13];
    const float* prod_lin_W1  = (const float*)d_in[14];

    int N_ = in_sizes[0] / 3;
    int E_ = in_sizes[2] / 2;

    size_t smemE = (size_t)SME_TOT * 4;
    size_t smemP = (size_t)SMP_TOT * 4;
    cudaFuncSetAttribute(k_edge<true>,  cudaFuncAttributeMaxDynamicSharedMemorySize, (int)smemE);
    cudaFuncSetAttribute(k_edge<false>, cudaFuncAttributeMaxDynamicSharedMemorySize, (int)smemE);
    cudaFuncSetAttribute(k_post<true>,  cudaFuncAttributeMaxDynamicSharedMemorySize, (int)smemP);
    cudaFuncSetAttribute(k_post<false>, cudaFuncAttributeMaxDynamicSharedMemorySize, (int)smemP);

    k_geom<<<(E_ + 255) / 256, 256>>>(positions, edge_index, E_);
    k_prepw<<<17, 256>>>(node_embed_W, lin_up_W0,
                         prod_lin_W0, lin_up_W0 + 4096,
                         prod_lin_W1, lin_up_W1 + 4096);
    k_seed<<<(N_ * CCH + 255) / 256, 256>>>(species, N_);

    void* p0;
    void* p1;
    cudaGetSymbolAddress(&p0, d_W0c);
    cudaGetSymbolAddress(&p1, d_W1c);
    const float* W0c_sym = (const float*)p0;
    const float* W1c_sym = (const float*)p1;

    // layer 0
    k_edge<true><<<EGRID, ETHREADS, smemE>>>(edge_index, mlp_W1, mlp_W2, mlp_W3, E_);
    k_post<false><<<(N_ + 63) / 64, 256, smemP>>>(
        species, lin_W0, lin_W1, prod_W0, prod_W1,
        W0c_sym, W1c_sym, nullptr, N_);

    // layer 1
    k_edge<false><<<EGRID, ETHREADS, smemE>>>(
        edge_index, mlp_W1 + 512, mlp_W2 + 4096, mlp_W3 + 20480, E_);
    k_post<true><<<(N_ + 63) / 64, 256, smemP>>>(
        species, lin_W0 + 4096, lin_W1 + 4096,
        prod_W0 + 768, prod_W1 + 512,
        prod_lin_W0 + 4096, prod_lin_W1 + 4096,
        (float4*)d_out, N_);
}